// round 3
// baseline (speedup 1.0000x reference)
#include <cuda_runtime.h>
#include <cuda_bf16.h>
#include <cstdint>

// Problem constants
#define NV 128   // vocab
#define NE 64    // embed
#define NH 128   // hidden
#define NC 12    // classes
#define NB 2048  // batch
#define NT 256   // timesteps
#define MB 16    // batch tile per block
#define SROWB 144 // s0 smem row stride in BYTES (int8 tile, conflict-free ldsm)

// Scratch (device globals: no allocation allowed)
__device__ float g_Q[NV * NH];
__device__ __align__(16) signed char g_W1a[NH * NH];  // int8 hi term
__device__ __align__(16) signed char g_W1b[NH * NH];  // int8 lo term
__device__ float g_s1[NH];
__device__ float g_s2[NH];

// ---------------------------------------------------------------------------
// Merged prep kernel: grid 64 x 256 threads. Block blk handles vocab rows
// v = 2*blk, 2*blk+1 for the Q table, and W1 rows n = 2*blk, 2*blk+1 for the
// int8 split.
//   Q[v,h] = (emb[v,:]@W_in^T + b_in) @ W_lif0^T + b_lif0
//   W1[n,:] ~= s1[n]*A1[n,:] + s2[n]*A2[n,:]   (s8, per-row scales)
// ---------------------------------------------------------------------------
#define PREP_SMEM (NH * 129 * 4 + NH * 65 * 4 + 512 + 1024 + 32)
__global__ __launch_bounds__(256) void prep_kernel(
    const float* __restrict__ emb, const float* __restrict__ W_in,
    const float* __restrict__ b_in, const float* __restrict__ W_lif,
    const float* __restrict__ b_lif) {
    extern __shared__ float dsm[];
    float* wsh129 = dsm;                    // W_lif0 padded [128][129]
    float* wsh65 = dsm + NH * 129;          // W_in padded  [128][65]
    float* esh = wsh65 + NH * 65;           // 2 emb rows   [128]
    float* psh = esh + 128;                 // P rows       [2][128]
    float* red = psh + 256;                 // warp maxes   [8]

    const int tid = threadIdx.x;
    const int blk = blockIdx.x;
    const int half = tid >> 7;
    const int k = tid & 127;

    // ---- stage W_lif0 [128 x 128] padded ----
    for (int i = tid; i < NH * NH; i += 256) {
        int r = i >> 7, c = i & 127;
        wsh129[r * 129 + c] = W_lif[i];
    }
    // ---- stage W_in [128 x 64] padded ----
    for (int i = tid; i < NH * NE; i += 256) {
        int r = i >> 6, c = i & 63;
        wsh65[r * 65 + c] = W_in[i];
    }
    // ---- stage 2 emb rows ----
    for (int i = tid; i < 2 * NE; i += 256) esh[i] = emb[blk * 2 * NE + i];

    // ---- W1 row-max (for int8 split) ----
    const int n = 2 * blk + half;
    const float w = W_lif[NH * NH + n * NH + k];
    {
        float m = fabsf(w);
#pragma unroll
        for (int d = 16; d > 0; d >>= 1)
            m = fmaxf(m, __shfl_xor_sync(0xFFFFFFFFu, m, d));
        if ((tid & 31) == 0) red[tid >> 5] = m;
    }
    __syncthreads();

    // ---- int8 split ----
    {
        float m = fmaxf(fmaxf(red[half * 4 + 0], red[half * 4 + 1]),
                        fmaxf(red[half * 4 + 2], red[half * 4 + 3]));
        float s1 = m * (1.0f / 127.0f);
        float inv1 = 127.0f / m;
        int a1 = __float2int_rn(w * inv1);
        a1 = max(-127, min(127, a1));
        float r = w - s1 * (float)a1;
        float s2 = s1 * (1.0f / 254.0f);
        int a2 = __float2int_rn(r * (254.0f / s1));
        a2 = max(-127, min(127, a2));
        g_W1a[n * NH + k] = (signed char)a1;
        g_W1b[n * NH + k] = (signed char)a2;
        if (k == 0) {
            g_s1[n] = s1;
            g_s2[n] = s2;
        }
    }

    // ---- P[half,h] = emb_row(half) . W_in[h,:] + b_in[h] ----
    {
        const int h = k;
        float a0 = 0.f, a1 = 0.f, a2 = 0.f, a3 = 0.f;
#pragma unroll
        for (int e = 0; e < NE; e += 4) {
            a0 += esh[half * NE + e + 0] * wsh65[h * 65 + e + 0];
            a1 += esh[half * NE + e + 1] * wsh65[h * 65 + e + 1];
            a2 += esh[half * NE + e + 2] * wsh65[h * 65 + e + 2];
            a3 += esh[half * NE + e + 3] * wsh65[h * 65 + e + 3];
        }
        psh[half * NH + h] = (a0 + a1) + (a2 + a3) + b_in[h];
    }
    __syncthreads();

    // ---- Q[v,h] = P[half,:] . W_lif0[h,:] + b_lif0[h] ----
    {
        const int h = k;
        float a0 = 0.f, a1 = 0.f, a2 = 0.f, a3 = 0.f;
#pragma unroll 8
        for (int i = 0; i < NH; i += 4) {
            a0 += psh[half * NH + i + 0] * wsh129[h * 129 + i + 0];
            a1 += psh[half * NH + i + 1] * wsh129[h * 129 + i + 1];
            a2 += psh[half * NH + i + 2] * wsh129[h * 129 + i + 2];
            a3 += psh[half * NH + i + 3] * wsh129[h * 129 + i + 3];
        }
        g_Q[(2 * blk + half) * NH + h] = (a0 + a1) + (a2 + a3) + b_lif[h];
    }
}

// ---------------------------------------------------------------------------
// mma.sync m16n8k32 s8 -> s32 accumulate
// ---------------------------------------------------------------------------
__device__ __forceinline__ void mma_s8(int c[4], uint32_t a0, uint32_t a1,
                                       uint32_t a2, uint32_t a3, uint32_t b0,
                                       uint32_t b1) {
    asm volatile(
        "mma.sync.aligned.m16n8k32.row.col.s32.s8.s8.s32 "
        "{%0,%1,%2,%3},{%4,%5,%6,%7},{%8,%9},{%0,%1,%2,%3};"
        : "+r"(c[0]), "+r"(c[1]), "+r"(c[2]), "+r"(c[3])
        : "r"(a0), "r"(a1), "r"(a2), "r"(a3), "r"(b0), "r"(b1));
}

// smem layout (dynamic):
//   [0      , 65536 )  Q table        (128*128 f32)
//   [65536  , 81920 )  ids            (16*256  i32)
//   [81920  , 88064 )  W_cls          (12*128  f32)
//   [88064  , 92672 )  s0 tile x2     (2 * 16*144 int8)
//   [92672  , 100864)  acc spill      (16*128  f32)
#define SM_BYTES 100864

// Layer-0 step: update 8 membranes, write int8 spikes {0,1} into sbuf.
__device__ __forceinline__ void layer0_step(const int* idss, const float* Qs,
                                            signed char* sbuf, float v0[8],
                                            int bh, int hp, int t) {
#pragma unroll
    for (int j = 0; j < 8; j++) {
        int b = bh + j;
        int id = idss[b * NT + t];
        float q = Qs[id * NH + hp];
        float v = 0.8f * v0[j] + 0.2f * q;
        bool s = (v >= 1.0f);
        v0[j] = s ? 0.f : v;
        sbuf[b * SROWB + hp] = s ? (signed char)1 : (signed char)0;
    }
}

__global__ __launch_bounds__(256, 1) void snn_main_kernel(
    const int* __restrict__ ids, const float* __restrict__ b_lif,
    const float* __restrict__ W_cls, const float* __restrict__ b_cls,
    float* __restrict__ out) {
    extern __shared__ char smem[];
    float* Qs = (float*)smem;
    int* idss = (int*)(smem + 65536);
    float* wclss = (float*)(smem + 81920);
    signed char* s0s = (signed char*)(smem + 88064);  // [2][16][SROWB]
    float* accs = (float*)(smem + 92672);

    const int tid = threadIdx.x;
    const int lane = tid & 31;
    const int warp = tid >> 5;
    const int g = lane >> 2;    // fragment row group
    const int tig = lane & 3;   // thread in group
    const int b0 = blockIdx.x * MB;

    // ---- cooperative smem fills ----
    {
        const float4* src = (const float4*)g_Q;
        float4* dst = (float4*)Qs;
#pragma unroll
        for (int i = tid; i < NV * NH / 4; i += 256) dst[i] = src[i];
    }
    {
        const int4* src = (const int4*)(ids + b0 * NT);
        int4* dst = (int4*)idss;
#pragma unroll
        for (int i = tid; i < MB * NT / 4; i += 256) dst[i] = src[i];
    }
    {
        const float4* src = (const float4*)W_cls;
        float4* dst = (float4*)wclss;
        for (int i = tid; i < NC * NH / 4; i += 256) dst[i] = src[i];
    }

    // ---- register-resident B fragments: int8 terms, [kt][nt][reg] ----
    const int nb = warp * 16;  // this warp's 16 output-h slice
    uint32_t Ba[4][2][2], Bb[4][2][2];
#pragma unroll
    for (int kt = 0; kt < 4; kt++) {
#pragma unroll
        for (int nt = 0; nt < 2; nt++) {
            int n = nb + nt * 8 + g;
            int kb = kt * 32 + tig * 4;
            Ba[kt][nt][0] = *(const uint32_t*)(g_W1a + n * NH + kb);
            Ba[kt][nt][1] = *(const uint32_t*)(g_W1a + n * NH + kb + 16);
            Bb[kt][nt][0] = *(const uint32_t*)(g_W1b + n * NH + kb);
            Bb[kt][nt][1] = *(const uint32_t*)(g_W1b + n * NH + kb + 16);
        }
    }

    // per-output-column constants (columns n = nb + nt*8 + tig*2 + {0,1}):
    // vv = 0.8*v + ca*(0.2*s1) + cb*(0.2*s2) + 0.2*bias
    float s1s[2][2], s2s[2][2], bias_s[2][2];
#pragma unroll
    for (int nt = 0; nt < 2; nt++)
#pragma unroll
        for (int c = 0; c < 2; c++) {
            int n = nb + nt * 8 + tig * 2 + c;
            s1s[nt][c] = 0.2f * g_s1[n];
            s2s[nt][c] = 0.2f * g_s2[n];
            bias_s[nt][c] = 0.2f * b_lif[NH + n];
        }

    // layer-0 state: thread owns (hp, 8 consecutive b)
    const int hp = tid & (NH - 1);
    const int bh = (tid >> 7) * 8;
    float v0[8];
#pragma unroll
    for (int j = 0; j < 8; j++) v0[j] = 0.f;

    // layer-1 state in C-fragment layout
    float v1[2][4], accr[2][4];
#pragma unroll
    for (int nt = 0; nt < 2; nt++)
#pragma unroll
        for (int r = 0; r < 4; r++) { v1[nt][r] = 0.f; accr[nt][r] = 0.f; }

    // ldmatrix lane address (byte tile): row = lane&15, +16B for lanes>=16
    const int arow = lane & 15;
    const int acolb = (lane >= 16) ? 16 : 0;
    const uint32_t abase0 =
        (uint32_t)__cvta_generic_to_shared(s0s + arow * SROWB + acolb);
    const uint32_t abase1 = abase0 + MB * SROWB;

    __syncthreads();

    // prologue: layer-0 for t=0 into buffer 0
    layer0_step(idss, Qs, s0s, v0, bh, hp, 0);
    __syncthreads();

    // =================== time loop ===================
    for (int t = 0; t < NT; t++) {
        const int p = t & 1;

        // ---- A fragments for this step (4 k-chunks of 32 int8) ----
        uint32_t A[4][4];
        const uint32_t ab = p ? abase1 : abase0;
#pragma unroll
        for (int kt = 0; kt < 4; kt++) {
            asm volatile(
                "ldmatrix.sync.aligned.m8n8.x4.shared.b16 {%0,%1,%2,%3},[%4];"
                : "=r"(A[kt][0]), "=r"(A[kt][1]), "=r"(A[kt][2]),
                  "=r"(A[kt][3])
                : "r"(ab + kt * 32));
        }

        // ---- 4 independent s32 accumulator chains ----
        int ca[2][4], cb[2][4];
#pragma unroll
        for (int nt = 0; nt < 2; nt++)
#pragma unroll
            for (int r = 0; r < 4; r++) { ca[nt][r] = 0; cb[nt][r] = 0; }

#pragma unroll
        for (int kt = 0; kt < 4; kt++) {
            mma_s8(ca[0], A[kt][0], A[kt][1], A[kt][2], A[kt][3],
                   Ba[kt][0][0], Ba[kt][0][1]);
            mma_s8(ca[1], A[kt][0], A[kt][1], A[kt][2], A[kt][3],
                   Ba[kt][1][0], Ba[kt][1][1]);
            mma_s8(cb[0], A[kt][0], A[kt][1], A[kt][2], A[kt][3],
                   Bb[kt][0][0], Bb[kt][0][1]);
            mma_s8(cb[1], A[kt][0], A[kt][1], A[kt][2], A[kt][3],
                   Bb[kt][1][0], Bb[kt][1][1]);
        }

        // ---- layer-0 for t+1 overlaps the IMMA shadow ----
        if (t + 1 < NT)
            layer0_step(idss, Qs, s0s + (p ^ 1) * (MB * SROWB), v0, bh, hp,
                        t + 1);

        // ---- layer-1 membrane/spike/reset + spike accumulation ----
#pragma unroll
        for (int nt = 0; nt < 2; nt++)
#pragma unroll
            for (int r = 0; r < 4; r++) {
                float c1f = (float)ca[nt][r];
                float c2f = (float)cb[nt][r];
                float vv = fmaf(
                    c1f, s1s[nt][r & 1],
                    fmaf(c2f, s2s[nt][r & 1],
                         fmaf(0.8f, v1[nt][r], bias_s[nt][r & 1])));
                bool s = (vv >= 1.0f);
                accr[nt][r] += s ? 1.f : 0.f;
                v1[nt][r] = s ? 0.f : vv;
            }

        __syncthreads();  // sole barrier: publishes s0(t+1), protects buf p
    }

    // =================== epilogue: classifier ===================
#pragma unroll
    for (int nt = 0; nt < 2; nt++)
#pragma unroll
        for (int r = 0; r < 4; r++) {
            int bl = (r < 2) ? g : (g + 8);
            int col = nb + nt * 8 + tig * 2 + (r & 1);
            accs[bl * NH + col] = accr[nt][r];
        }
    __syncthreads();

    if (tid < MB * NC) {
        int bl = tid / NC;
        int cc = tid % NC;
        float sum = 0.f;
#pragma unroll 8
        for (int h = 0; h < NH; h++) sum += accs[bl * NH + h] * wclss[cc * NH + h];
        out[(b0 + bl) * NC + cc] = sum * (1.0f / NT) + b_cls[cc];
    }
}

// ---------------------------------------------------------------------------
// Host launcher (graph-capturable: kernel launches only)
// Input order: ids, emb, W_in, b_in, W_lif, b_lif, W_rec(unused), W_cls, b_cls
// ---------------------------------------------------------------------------
extern "C" void kernel_launch(void* const* d_in, const int* in_sizes, int n_in,
                              void* d_out, int out_size) {
    const int* ids = (const int*)d_in[0];
    const float* emb = (const float*)d_in[1];
    const float* W_in = (const float*)d_in[2];
    const float* b_in = (const float*)d_in[3];
    const float* W_lif = (const float*)d_in[4];
    const float* b_lif = (const float*)d_in[5];
    const float* W_cls = (const float*)d_in[7];
    const float* b_cls = (const float*)d_in[8];
    float* out = (float*)d_out;

    cudaFuncSetAttribute(prep_kernel,
                         cudaFuncAttributeMaxDynamicSharedMemorySize, PREP_SMEM);
    cudaFuncSetAttribute(snn_main_kernel,
                         cudaFuncAttributeMaxDynamicSharedMemorySize, SM_BYTES);

    prep_kernel<<<NV / 2, 256, PREP_SMEM>>>(emb, W_in, b_in, W_lif, b_lif);
    snn_main_kernel<<<NB / MB, 256, SM_BYTES>>>(ids, b_lif, W_cls, b_cls, out);
}

// round 4
// speedup vs baseline: 5.1353x; 5.1353x over previous
#include <cuda_runtime.h>
#include <cuda_bf16.h>
#include <cstdint>

// Problem constants
#define NV 128   // vocab
#define NE 64    // embed
#define NH 128   // hidden
#define NC 12    // classes
#define NB 2048  // batch
#define NT 256   // timesteps
#define MB 16    // batch tile per block
#define SROW 136 // s0 smem row stride in bf16 elements

// Scratch (device globals: no allocation allowed)
__device__ float g_Q[NV * NH];
__device__ __align__(16) unsigned short g_W1hi[NH * NH];
__device__ __align__(16) unsigned short g_W1lo[NH * NH];

// ---------------------------------------------------------------------------
// Merged prep kernel: 64 blocks x 256 threads. Block blk computes Q rows
// v = 2*blk, 2*blk+1 and the bf16 hi/lo split for 256 W_lif1 elements.
//   Q[v,h] = (emb[v,:]@W_in^T + b_in) @ W_lif0^T + b_lif0
// ---------------------------------------------------------------------------
#define PREP_SMEM (NH * 129 * 4 + NH * 65 * 4 + 512 + 1024)
__global__ __launch_bounds__(256) void prep_kernel(
    const float* __restrict__ emb, const float* __restrict__ W_in,
    const float* __restrict__ b_in, const float* __restrict__ W_lif,
    const float* __restrict__ b_lif) {
    extern __shared__ float dsm[];
    float* wsh129 = dsm;                    // W_lif0 padded [128][129]
    float* wsh65 = dsm + NH * 129;          // W_in padded  [128][65]
    float* esh = wsh65 + NH * 65;           // 2 emb rows   [128]
    float* psh = esh + 128;                 // P rows       [2][128]

    const int tid = threadIdx.x;
    const int blk = blockIdx.x;
    const int half = tid >> 7;
    const int h = tid & 127;

    // ---- W_lif1 bf16 hi/lo split (exact 2-term) ----
    {
        const int gid = blk * 256 + tid;  // covers NH*NH exactly
        float w = W_lif[NH * NH + gid];
        __nv_bfloat16 hi = __float2bfloat16(w);
        float rem = w - __bfloat162float(hi);
        __nv_bfloat16 lo = __float2bfloat16(rem);
        g_W1hi[gid] = *reinterpret_cast<unsigned short*>(&hi);
        g_W1lo[gid] = *reinterpret_cast<unsigned short*>(&lo);
    }

    // ---- stage W_lif0 [128 x 128] padded ----
    for (int i = tid; i < NH * NH; i += 256) {
        int r = i >> 7, c = i & 127;
        wsh129[r * 129 + c] = W_lif[i];
    }
    // ---- stage W_in [128 x 64] padded ----
    for (int i = tid; i < NH * NE; i += 256) {
        int r = i >> 6, c = i & 63;
        wsh65[r * 65 + c] = W_in[i];
    }
    // ---- stage 2 emb rows ----
    for (int i = tid; i < 2 * NE; i += 256) esh[i] = emb[blk * 2 * NE + i];
    __syncthreads();

    // ---- P[half,h] = emb_row(half) . W_in[h,:] + b_in[h] ----
    {
        float a0 = 0.f, a1 = 0.f, a2 = 0.f, a3 = 0.f;
#pragma unroll
        for (int e = 0; e < NE; e += 4) {
            a0 += esh[half * NE + e + 0] * wsh65[h * 65 + e + 0];
            a1 += esh[half * NE + e + 1] * wsh65[h * 65 + e + 1];
            a2 += esh[half * NE + e + 2] * wsh65[h * 65 + e + 2];
            a3 += esh[half * NE + e + 3] * wsh65[h * 65 + e + 3];
        }
        psh[half * NH + h] = (a0 + a1) + (a2 + a3) + b_in[h];
    }
    __syncthreads();

    // ---- Q[v,h] = P[half,:] . W_lif0[h,:] + b_lif0[h] ----
    {
        float a0 = 0.f, a1 = 0.f, a2 = 0.f, a3 = 0.f;
#pragma unroll 8
        for (int i = 0; i < NH; i += 4) {
            a0 += psh[half * NH + i + 0] * wsh129[h * 129 + i + 0];
            a1 += psh[half * NH + i + 1] * wsh129[h * 129 + i + 1];
            a2 += psh[half * NH + i + 2] * wsh129[h * 129 + i + 2];
            a3 += psh[half * NH + i + 3] * wsh129[h * 129 + i + 3];
        }
        g_Q[(2 * blk + half) * NH + h] = (a0 + a1) + (a2 + a3) + b_lif[h];
    }
}

// ---------------------------------------------------------------------------
// mma.sync m16n8k16 bf16 -> fp32 accumulate
// ---------------------------------------------------------------------------
__device__ __forceinline__ void mma_bf16(float c[4], uint32_t a0, uint32_t a1,
                                         uint32_t a2, uint32_t a3,
                                         uint32_t b0, uint32_t b1) {
    asm volatile(
        "mma.sync.aligned.m16n8k16.row.col.f32.bf16.bf16.f32 "
        "{%0,%1,%2,%3},{%4,%5,%6,%7},{%8,%9},{%0,%1,%2,%3};"
        : "+f"(c[0]), "+f"(c[1]), "+f"(c[2]), "+f"(c[3])
        : "r"(a0), "r"(a1), "r"(a2), "r"(a3), "r"(b0), "r"(b1));
}

// smem layout (dynamic):
//   [0      , 65536 )  Q table        (128*128 f32)
//   [65536  , 81920 )  ids            (16*256  i32)
//   [81920  , 88064 )  W_cls          (12*128  f32)
//   [88064  , 92416 )  s0 tile        (16*136  bf16)
//   [92416  , 100608)  acc spill      (16*128  f32)
#define SM_BYTES 100608

__global__ __launch_bounds__(256, 1) void snn_main_kernel(
    const int* __restrict__ ids, const float* __restrict__ b_lif,
    const float* __restrict__ W_cls, const float* __restrict__ b_cls,
    float* __restrict__ out) {
    extern __shared__ char smem[];
    float* Qs = (float*)smem;
    int* idss = (int*)(smem + 65536);
    float* wclss = (float*)(smem + 81920);
    unsigned short* s0s = (unsigned short*)(smem + 88064);
    float* accs = (float*)(smem + 92416);

    const int tid = threadIdx.x;
    const int lane = tid & 31;
    const int warp = tid >> 5;
    const int g = lane >> 2;    // fragment row group
    const int tig = lane & 3;   // thread in group
    const int b0 = blockIdx.x * MB;

    // ---- cooperative smem fills ----
    {
        const float4* src = (const float4*)g_Q;
        float4* dst = (float4*)Qs;
#pragma unroll
        for (int i = tid; i < NV * NH / 4; i += 256) dst[i] = src[i];
    }
    {
        const int4* src = (const int4*)(ids + b0 * NT);
        int4* dst = (int4*)idss;
#pragma unroll
        for (int i = tid; i < MB * NT / 4; i += 256) dst[i] = src[i];
    }
    {
        const float4* src = (const float4*)W_cls;
        float4* dst = (float4*)wclss;
        for (int i = tid; i < NC * NH / 4; i += 256) dst[i] = src[i];
    }

    // ---- register-resident B fragments: W1 hi/lo, [kt][nt][reg] ----
    const int nb = warp * 16;  // this warp's 16 output-h slice
    uint32_t Bhi[8][2][2], Blo[8][2][2];
#pragma unroll
    for (int kt = 0; kt < 8; kt++) {
#pragma unroll
        for (int nt = 0; nt < 2; nt++) {
            int n = nb + nt * 8 + g;
            int k = kt * 16 + tig * 2;
            Bhi[kt][nt][0] = *(const uint32_t*)(g_W1hi + n * NH + k);
            Bhi[kt][nt][1] = *(const uint32_t*)(g_W1hi + n * NH + k + 8);
            Blo[kt][nt][0] = *(const uint32_t*)(g_W1lo + n * NH + k);
            Blo[kt][nt][1] = *(const uint32_t*)(g_W1lo + n * NH + k + 8);
        }
    }

    // bias (layer 1) at this thread's C-fragment columns
    float bias[2][2];
#pragma unroll
    for (int nt = 0; nt < 2; nt++) {
        bias[nt][0] = b_lif[NH + nb + nt * 8 + tig * 2];
        bias[nt][1] = b_lif[NH + nb + nt * 8 + tig * 2 + 1];
    }

    // layer-0 state: thread owns (hp, 8 consecutive b)
    const int hp = tid & (NH - 1);
    const int bh = (tid >> 7) * 8;
    float v0[8];
#pragma unroll
    for (int j = 0; j < 8; j++) v0[j] = 0.f;

    // layer-1 state in C-fragment layout
    float v1[2][4], accr[2][4];
#pragma unroll
    for (int nt = 0; nt < 2; nt++)
#pragma unroll
        for (int r = 0; r < 4; r++) { v1[nt][r] = 0.f; accr[nt][r] = 0.f; }

    // ldmatrix lane address: row = lane&15, +8 cols for lanes>=16
    const int arow = lane & 15;
    const int acol = (lane >= 16) ? 8 : 0;
    const uint32_t abase =
        (uint32_t)__cvta_generic_to_shared(s0s + arow * SROW + acol);

    __syncthreads();

    // =================== time loop ===================
    for (int t = 0; t < NT; t++) {
        // ---- layer 0: membrane update in registers, collect spike mask ----
        int smask = 0;
#pragma unroll
        for (int j = 0; j < 8; j++) {
            int b = bh + j;
            int id = idss[b * NT + t];
            float q = Qs[id * NH + hp];
            float v = 0.8f * v0[j] + 0.2f * q;
            bool s = (v >= 1.0f);
            v0[j] = s ? 0.f : v;
            smask |= (s ? (1 << j) : 0);
        }

        // block-wide spike detection (this is also our barrier)
        int any = __syncthreads_or(smask);

        if (any) {
            // ---------- SLOW PATH: real spikes -> full bf16 hi/lo MMA ----------
#pragma unroll
            for (int j = 0; j < 8; j++) {
                int b = bh + j;
                s0s[b * SROW + hp] = (smask >> j) & 1
                                         ? (unsigned short)0x3F80
                                         : (unsigned short)0;
            }
            __syncthreads();

            float chi[2][4], clo[2][4];
#pragma unroll
            for (int nt = 0; nt < 2; nt++)
#pragma unroll
                for (int r = 0; r < 4; r++) { chi[nt][r] = 0.f; clo[nt][r] = 0.f; }

#pragma unroll
            for (int kt = 0; kt < 8; kt++) {
                uint32_t a0, a1, a2, a3;
                asm volatile(
                    "ldmatrix.sync.aligned.m8n8.x4.shared.b16 {%0,%1,%2,%3},[%4];"
                    : "=r"(a0), "=r"(a1), "=r"(a2), "=r"(a3)
                    : "r"(abase + kt * 32));
                mma_bf16(chi[0], a0, a1, a2, a3, Bhi[kt][0][0], Bhi[kt][0][1]);
                mma_bf16(chi[1], a0, a1, a2, a3, Bhi[kt][1][0], Bhi[kt][1][1]);
                mma_bf16(clo[0], a0, a1, a2, a3, Blo[kt][0][0], Blo[kt][0][1]);
                mma_bf16(clo[1], a0, a1, a2, a3, Blo[kt][1][0], Blo[kt][1][1]);
            }

#pragma unroll
            for (int nt = 0; nt < 2; nt++)
#pragma unroll
                for (int r = 0; r < 4; r++) {
                    float cur = chi[nt][r] + clo[nt][r] + bias[nt][r & 1];
                    float vv = 0.8f * v1[nt][r] + 0.2f * cur;
                    bool s = (vv >= 1.0f);
                    accr[nt][r] += s ? 1.f : 0.f;
                    v1[nt][r] = s ? 0.f : vv;
                }
        } else {
            // ---------- FAST PATH: no spikes anywhere -> cur == 0 ----------
            // (bit-identical to slow path with chi=clo=0)
#pragma unroll
            for (int nt = 0; nt < 2; nt++)
#pragma unroll
                for (int r = 0; r < 4; r++) {
                    float cur = bias[nt][r & 1];
                    float vv = 0.8f * v1[nt][r] + 0.2f * cur;
                    bool s = (vv >= 1.0f);
                    accr[nt][r] += s ? 1.f : 0.f;
                    v1[nt][r] = s ? 0.f : vv;
                }
        }
    }

    // =================== epilogue: classifier ===================
#pragma unroll
    for (int nt = 0; nt < 2; nt++)
#pragma unroll
        for (int r = 0; r < 4; r++) {
            int bl = (r < 2) ? g : (g + 8);
            int col = nb + nt * 8 + tig * 2 + (r & 1);
            accs[bl * NH + col] = accr[nt][r];
        }
    __syncthreads();

    if (tid < MB * NC) {
        int bl = tid / NC;
        int cc = tid % NC;
        float sum = 0.f;
#pragma unroll 8
        for (int h = 0; h < NH; h++) sum += accs[bl * NH + h] * wclss[cc * NH + h];
        out[(b0 + bl) * NC + cc] = sum * (1.0f / NT) + b_cls[cc];
    }
}

// ---------------------------------------------------------------------------
// Host launcher (graph-capturable: kernel launches only)
// Input order: ids, emb, W_in, b_in, W_lif, b_lif, W_rec(unused), W_cls, b_cls
// ---------------------------------------------------------------------------
extern "C" void kernel_launch(void* const* d_in, const int* in_sizes, int n_in,
                              void* d_out, int out_size) {
    const int* ids = (const int*)d_in[0];
    const float* emb = (const float*)d_in[1];
    const float* W_in = (const float*)d_in[2];
    const float* b_in = (const float*)d_in[3];
    const float* W_lif = (const float*)d_in[4];
    const float* b_lif = (const float*)d_in[5];
    const float* W_cls = (const float*)d_in[7];
    const float* b_cls = (const float*)d_in[8];
    float* out = (float*)d_out;

    cudaFuncSetAttribute(prep_kernel,
                         cudaFuncAttributeMaxDynamicSharedMemorySize, PREP_SMEM);
    cudaFuncSetAttribute(snn_main_kernel,
                         cudaFuncAttributeMaxDynamicSharedMemorySize, SM_BYTES);

    prep_kernel<<<NV / 2, 256, PREP_SMEM>>>(emb, W_in, b_in, W_lif, b_lif);
    snn_main_kernel<<<NB / MB, 256, SM_BYTES>>>(ids, b_lif, W_cls, b_cls, out);
}

// round 5
// speedup vs baseline: 6.8896x; 1.3416x over previous
#include <cuda_runtime.h>
#include <cuda_bf16.h>
#include <cstdint>

// Problem constants
#define NV 128   // vocab
#define NE 64    // embed
#define NH 128   // hidden
#define NC 12    // classes
#define NB 2048  // batch
#define NT 256   // timesteps
#define MB 16    // batch tile per block
#define SROW 136 // s0 smem row stride in bf16 elements
#define NTHR 512

// Scratch (device globals: no allocation allowed)
__device__ float g_Q[NV * NH];
__device__ __align__(16) unsigned short g_W1hi[NH * NH];
__device__ __align__(16) unsigned short g_W1lo[NH * NH];

// ---------------------------------------------------------------------------
// Merged prep kernel: 64 blocks x 256 threads. Block blk computes Q rows
// v = 2*blk, 2*blk+1 and the bf16 hi/lo split for 256 W_lif1 elements.
//   Q[v,h] = (emb[v,:]@W_in^T + b_in) @ W_lif0^T + b_lif0
// ---------------------------------------------------------------------------
#define PREP_SMEM (NH * 129 * 4 + NH * 65 * 4 + 512 + 1024)
__global__ __launch_bounds__(256) void prep_kernel(
    const float* __restrict__ emb, const float* __restrict__ W_in,
    const float* __restrict__ b_in, const float* __restrict__ W_lif,
    const float* __restrict__ b_lif) {
    extern __shared__ float dsm[];
    float* wsh129 = dsm;                    // W_lif0 padded [128][129]
    float* wsh65 = dsm + NH * 129;          // W_in padded  [128][65]
    float* esh = wsh65 + NH * 65;           // 2 emb rows   [128]
    float* psh = esh + 128;                 // P rows       [2][128]

    const int tid = threadIdx.x;
    const int blk = blockIdx.x;
    const int half = tid >> 7;
    const int h = tid & 127;

    // ---- W_lif1 bf16 hi/lo split (exact 2-term) ----
    {
        const int gid = blk * 256 + tid;  // covers NH*NH exactly
        float w = W_lif[NH * NH + gid];
        __nv_bfloat16 hi = __float2bfloat16(w);
        float rem = w - __bfloat162float(hi);
        __nv_bfloat16 lo = __float2bfloat16(rem);
        g_W1hi[gid] = *reinterpret_cast<unsigned short*>(&hi);
        g_W1lo[gid] = *reinterpret_cast<unsigned short*>(&lo);
    }

    // ---- stage W_lif0 [128 x 128] padded ----
    for (int i = tid; i < NH * NH; i += 256) {
        int r = i >> 7, c = i & 127;
        wsh129[r * 129 + c] = W_lif[i];
    }
    // ---- stage W_in [128 x 64] padded ----
    for (int i = tid; i < NH * NE; i += 256) {
        int r = i >> 6, c = i & 63;
        wsh65[r * 65 + c] = W_in[i];
    }
    // ---- stage 2 emb rows ----
    for (int i = tid; i < 2 * NE; i += 256) esh[i] = emb[blk * 2 * NE + i];
    __syncthreads();

    // ---- P[half,h] = emb_row(half) . W_in[h,:] + b_in[h] ----
    {
        float a0 = 0.f, a1 = 0.f, a2 = 0.f, a3 = 0.f;
#pragma unroll
        for (int e = 0; e < NE; e += 4) {
            a0 += esh[half * NE + e + 0] * wsh65[h * 65 + e + 0];
            a1 += esh[half * NE + e + 1] * wsh65[h * 65 + e + 1];
            a2 += esh[half * NE + e + 2] * wsh65[h * 65 + e + 2];
            a3 += esh[half * NE + e + 3] * wsh65[h * 65 + e + 3];
        }
        psh[half * NH + h] = (a0 + a1) + (a2 + a3) + b_in[h];
    }
    __syncthreads();

    // ---- Q[v,h] = P[half,:] . W_lif0[h,:] + b_lif0[h] ----
    {
        float a0 = 0.f, a1 = 0.f, a2 = 0.f, a3 = 0.f;
#pragma unroll 8
        for (int i = 0; i < NH; i += 4) {
            a0 += psh[half * NH + i + 0] * wsh129[h * 129 + i + 0];
            a1 += psh[half * NH + i + 1] * wsh129[h * 129 + i + 1];
            a2 += psh[half * NH + i + 2] * wsh129[h * 129 + i + 2];
            a3 += psh[half * NH + i + 3] * wsh129[h * 129 + i + 3];
        }
        g_Q[(2 * blk + half) * NH + h] = (a0 + a1) + (a2 + a3) + b_lif[h];
    }
}

// ---------------------------------------------------------------------------
// mma.sync m16n8k16 bf16 -> fp32 accumulate
// ---------------------------------------------------------------------------
__device__ __forceinline__ void mma_bf16(float c[4], uint32_t a0, uint32_t a1,
                                         uint32_t a2, uint32_t a3,
                                         uint32_t b0, uint32_t b1) {
    asm volatile(
        "mma.sync.aligned.m16n8k16.row.col.f32.bf16.bf16.f32 "
        "{%0,%1,%2,%3},{%4,%5,%6,%7},{%8,%9},{%0,%1,%2,%3};"
        : "+f"(c[0]), "+f"(c[1]), "+f"(c[2]), "+f"(c[3])
        : "r"(a0), "r"(a1), "r"(a2), "r"(a3), "r"(b0), "r"(b1));
}

// smem layout (dynamic):
//   [0      , 65536 )  Q table        (128*128 f32)
//   [65536  , 81920 )  ids            (16*256  i32)
//   [81920  , 88064 )  W_cls          (12*128  f32)
//   [88064  , 92416 )  s0 tile        (16*136  bf16)
//   [92416  , 100608)  acc spill      (16*128  f32)
#define SM_BYTES 100608

__global__ __launch_bounds__(NTHR, 1) void snn_main_kernel(
    const int* __restrict__ ids, const float* __restrict__ b_lif,
    const float* __restrict__ W_cls, const float* __restrict__ b_cls,
    float* __restrict__ out) {
    extern __shared__ char smem[];
    float* Qs = (float*)smem;
    int* idss = (int*)(smem + 65536);
    float* wclss = (float*)(smem + 81920);
    unsigned short* s0s = (unsigned short*)(smem + 88064);
    float* accs = (float*)(smem + 92416);

    const int tid = threadIdx.x;
    const int lane = tid & 31;
    const int warp = tid >> 5;  // 0..15
    const int g = lane >> 2;    // fragment row group
    const int tig = lane & 3;   // thread in group
    const int b0 = blockIdx.x * MB;

    // ---- cooperative smem fills ----
    {
        const float4* src = (const float4*)g_Q;
        float4* dst = (float4*)Qs;
#pragma unroll
        for (int i = tid; i < NV * NH / 4; i += NTHR) dst[i] = src[i];
    }
    {
        const int4* src = (const int4*)(ids + b0 * NT);
        int4* dst = (int4*)idss;
#pragma unroll
        for (int i = tid; i < MB * NT / 4; i += NTHR) dst[i] = src[i];
    }
    {
        const float4* src = (const float4*)W_cls;
        float4* dst = (float4*)wclss;
        for (int i = tid; i < NC * NH / 4; i += NTHR) dst[i] = src[i];
    }

    // ---- register-resident B fragments: W1 hi/lo ----
    // 16 warps x 8 output columns each: n = warp*8 + g over kt
    const int nb = warp * 8;
    uint32_t Bhi[8][2], Blo[8][2];
#pragma unroll
    for (int kt = 0; kt < 8; kt++) {
        int n = nb + g;
        int k = kt * 16 + tig * 2;
        Bhi[kt][0] = *(const uint32_t*)(g_W1hi + n * NH + k);
        Bhi[kt][1] = *(const uint32_t*)(g_W1hi + n * NH + k + 8);
        Blo[kt][0] = *(const uint32_t*)(g_W1lo + n * NH + k);
        Blo[kt][1] = *(const uint32_t*)(g_W1lo + n * NH + k + 8);
    }

    // bias (layer 1) at this thread's C-fragment columns
    float bias[2];
    bias[0] = b_lif[NH + nb + tig * 2];
    bias[1] = b_lif[NH + nb + tig * 2 + 1];

    // layer-0 state: thread owns (batch bb, 4 consecutive h)
    const int bb = tid >> 5;           // warp-uniform batch index
    const int h4 = (tid & 31) * 4;     // 4 consecutive hidden dims
    float v0[4];
#pragma unroll
    for (int j = 0; j < 4; j++) v0[j] = 0.f;

    // layer-1 state in C-fragment layout (4 values)
    float v1[4], accr[4];
#pragma unroll
    for (int r = 0; r < 4; r++) { v1[r] = 0.f; accr[r] = 0.f; }

    // ldmatrix lane address: row = lane&15, +8 cols for lanes>=16
    const int arow = lane & 15;
    const int acol = (lane >= 16) ? 8 : 0;
    const uint32_t abase =
        (uint32_t)__cvta_generic_to_shared(s0s + arow * SROW + acol);

    __syncthreads();

    // =================== time loop: 64 groups of 4 steps ===================
    for (int tb = 0; tb < NT / 4; tb++) {
        // ids for this batch, 4 steps (warp-uniform broadcast load)
        const int4 idv = *(const int4*)(idss + bb * NT + tb * 4);
        const int idk[4] = {idv.x, idv.y, idv.z, idv.w};

        // ---- layer 0: 4 sub-steps, masks collected ----
        int m[4];
#pragma unroll
        for (int k = 0; k < 4; k++) {
            const float4 q = *(const float4*)(Qs + idk[k] * NH + h4);
            const float qq[4] = {q.x, q.y, q.z, q.w};
            int mk = 0;
#pragma unroll
            for (int j = 0; j < 4; j++) {
                float v = 0.8f * v0[j] + 0.2f * qq[j];
                bool s = (v >= 1.0f);
                v0[j] = s ? 0.f : v;
                mk |= (s ? (1 << j) : 0);
            }
            m[k] = mk;
        }

        // single block-wide spike check for the whole group (also a barrier)
        const int any =
            __syncthreads_or(m[0] | m[1] | m[2] | m[3]);

        if (!any) {
            // ---------- FAST PATH: cur == 0 for all 4 steps ----------
#pragma unroll
            for (int k = 0; k < 4; k++)
#pragma unroll
                for (int r = 0; r < 4; r++) {
                    float cur = bias[r & 1];
                    float vv = 0.8f * v1[r] + 0.2f * cur;
                    bool s = (vv >= 1.0f);
                    accr[r] += s ? 1.f : 0.f;
                    v1[r] = s ? 0.f : vv;
                }
        } else {
            // ---------- SLOW GROUP: per-substep resolution ----------
#pragma unroll
            for (int k = 0; k < 4; k++) {
                const int anyk = __syncthreads_or(m[k]);
                if (anyk) {
                    // publish s0(k): 4 bf16 per thread
                    unsigned short* p = s0s + bb * SROW + h4;
                    p[0] = (m[k] & 1) ? (unsigned short)0x3F80 : 0;
                    p[1] = (m[k] & 2) ? (unsigned short)0x3F80 : 0;
                    p[2] = (m[k] & 4) ? (unsigned short)0x3F80 : 0;
                    p[3] = (m[k] & 8) ? (unsigned short)0x3F80 : 0;
                    __syncthreads();

                    float chi[4], clo[4];
#pragma unroll
                    for (int r = 0; r < 4; r++) { chi[r] = 0.f; clo[r] = 0.f; }
#pragma unroll
                    for (int kt = 0; kt < 8; kt++) {
                        uint32_t a0, a1, a2, a3;
                        asm volatile(
                            "ldmatrix.sync.aligned.m8n8.x4.shared.b16 "
                            "{%0,%1,%2,%3},[%4];"
                            : "=r"(a0), "=r"(a1), "=r"(a2), "=r"(a3)
                            : "r"(abase + kt * 32));
                        mma_bf16(chi, a0, a1, a2, a3, Bhi[kt][0], Bhi[kt][1]);
                        mma_bf16(clo, a0, a1, a2, a3, Blo[kt][0], Blo[kt][1]);
                    }
#pragma unroll
                    for (int r = 0; r < 4; r++) {
                        float cur = chi[r] + clo[r] + bias[r & 1];
                        float vv = 0.8f * v1[r] + 0.2f * cur;
                        bool s = (vv >= 1.0f);
                        accr[r] += s ? 1.f : 0.f;
                        v1[r] = s ? 0.f : vv;
                    }
                    // next write to s0 is guarded by the next
                    // __syncthreads_or barrier, so no extra barrier here
                } else {
#pragma unroll
                    for (int r = 0; r < 4; r++) {
                        float cur = bias[r & 1];
                        float vv = 0.8f * v1[r] + 0.2f * cur;
                        bool s = (vv >= 1.0f);
                        accr[r] += s ? 1.f : 0.f;
                        v1[r] = s ? 0.f : vv;
                    }
                }
            }
        }
    }

    // =================== epilogue: classifier ===================
#pragma unroll
    for (int r = 0; r < 4; r++) {
        int bl = (r < 2) ? g : (g + 8);
        int col = nb + tig * 2 + (r & 1);
        accs[bl * NH + col] = accr[r];
    }
    __syncthreads();

    if (tid < MB * NC) {
        int bl = tid / NC;
        int cc = tid % NC;
        float sum = 0.f;
#pragma unroll 8
        for (int h = 0; h < NH; h++) sum += accs[bl * NH + h] * wclss[cc * NH + h];
        out[(b0 + bl) * NC + cc] = sum * (1.0f / NT) + b_cls[cc];
    }
}

// ---------------------------------------------------------------------------
// Host launcher (graph-capturable: kernel launches only)
// Input order: ids, emb, W_in, b_in, W_lif, b_lif, W_rec(unused), W_cls, b_cls
// ---------------------------------------------------------------------------
extern "C" void kernel_launch(void* const* d_in, const int* in_sizes, int n_in,
                              void* d_out, int out_size) {
    const int* ids = (const int*)d_in[0];
    const float* emb = (const float*)d_in[1];
    const float* W_in = (const float*)d_in[2];
    const float* b_in = (const float*)d_in[3];
    const float* W_lif = (const float*)d_in[4];
    const float* b_lif = (const float*)d_in[5];
    const float* W_cls = (const float*)d_in[7];
    const float* b_cls = (const float*)d_in[8];
    float* out = (float*)d_out;

    cudaFuncSetAttribute(prep_kernel,
                         cudaFuncAttributeMaxDynamicSharedMemorySize, PREP_SMEM);
    cudaFuncSetAttribute(snn_main_kernel,
                         cudaFuncAttributeMaxDynamicSharedMemorySize, SM_BYTES);

    prep_kernel<<<NV / 2, 256, PREP_SMEM>>>(emb, W_in, b_in, W_lif, b_lif);
    snn_main_kernel<<<NB / MB, NTHR, SM_BYTES>>>(ids, b_lif, W_cls, b_cls, out);
}

// round 6
// speedup vs baseline: 9.6745x; 1.4042x over previous
#include <cuda_runtime.h>
#include <cuda_bf16.h>
#include <cstdint>

// Problem constants
#define NV 128   // vocab
#define NE 64    // embed
#define NH 128   // hidden
#define NC 12    // classes
#define NB 2048  // batch
#define NT 256   // timesteps
#define MB 16    // batch tile per block (one warp per batch)
#define NTHR 512

// Scratch (device global: no allocation allowed)
// g_Q stores 0.2f * ((emb[v]@W_in^T + b_in) @ W_lif0^T + b_lif0)
__device__ float g_Q[NV * NH];

// ---------------------------------------------------------------------------
// Prep kernel: 128 blocks x 128 threads; block v, thread h.
// ---------------------------------------------------------------------------
__global__ __launch_bounds__(128) void prep_kernel(
    const float* __restrict__ emb, const float* __restrict__ W_in,
    const float* __restrict__ b_in, const float* __restrict__ W_lif,
    const float* __restrict__ b_lif) {
    __shared__ float esh[NE];
    __shared__ float psh[NH];
    const int v = blockIdx.x;
    const int h = threadIdx.x;

    if (h < NE) esh[h] = emb[v * NE + h];
    __syncthreads();

    // P[h] = emb[v,:] . W_in[h,:] + b_in[h]
    {
        const float* wr = W_in + h * NE;
        float a0 = 0.f, a1 = 0.f, a2 = 0.f, a3 = 0.f;
#pragma unroll
        for (int e = 0; e < NE; e += 4) {
            a0 += esh[e + 0] * __ldg(wr + e + 0);
            a1 += esh[e + 1] * __ldg(wr + e + 1);
            a2 += esh[e + 2] * __ldg(wr + e + 2);
            a3 += esh[e + 3] * __ldg(wr + e + 3);
        }
        psh[h] = (a0 + a1) + (a2 + a3) + b_in[h];
    }
    __syncthreads();

    // Q[v,h] = 0.2 * (P . W_lif0[h,:] + b_lif0[h])
    {
        const float* wr = W_lif + h * NH;
        float a0 = 0.f, a1 = 0.f, a2 = 0.f, a3 = 0.f;
#pragma unroll 8
        for (int i = 0; i < NH; i += 4) {
            a0 += psh[i + 0] * __ldg(wr + i + 0);
            a1 += psh[i + 1] * __ldg(wr + i + 1);
            a2 += psh[i + 2] * __ldg(wr + i + 2);
            a3 += psh[i + 3] * __ldg(wr + i + 3);
        }
        g_Q[v * NH + h] = 0.2f * ((a0 + a1) + (a2 + a3) + b_lif[h]);
    }
}

// smem layout (dynamic):
//   [0     , 65536)  Q table (128*128 f32, pre-scaled by 0.2)
//   [65536 , 81920)  ids     (16*256 i32)
//   [81920 , 82948)  pow08   (257 f32)
#define SM_BYTES 82960

__global__ __launch_bounds__(NTHR, 1) void snn_main_kernel(
    const int* __restrict__ ids, const float* __restrict__ W_lif,
    const float* __restrict__ b_lif, const float* __restrict__ W_cls,
    const float* __restrict__ b_cls, float* __restrict__ out) {
    extern __shared__ char smem[];
    float* Qs = (float*)smem;
    int* idss = (int*)(smem + 65536);
    float* pow08 = (float*)(smem + 81920);

    const int tid = threadIdx.x;
    const int lane = tid & 31;
    const int warp = tid >> 5;  // warp == batch within tile (0..15)
    const int b0 = blockIdx.x * MB;
    const int h4 = lane * 4;    // this thread's 4 hidden dims (both layers)

    // ---- cooperative smem fills ----
    {
        const float4* src = (const float4*)g_Q;
        float4* dst = (float4*)Qs;
#pragma unroll
        for (int i = tid; i < NV * NH / 4; i += NTHR) dst[i] = src[i];
    }
    {
        const int4* src = (const int4*)(ids + b0 * NT);
        int4* dst = (int4*)idss;
#pragma unroll
        for (int i = tid; i < MB * NT / 4; i += NTHR) dst[i] = src[i];
    }
    // 0.8^n table via repeated squaring (used only on rare spike events)
    if (tid <= NT) {
        float p = 1.f, b = 0.8f;
        int n = tid;
#pragma unroll
        for (int k = 0; k < 9; k++) {
            if (n & 1) p *= b;
            b *= b;
            n >>= 1;
        }
        pow08[tid] = p;
    }

    // layer-1 per-thread constants
    const float* W1 = W_lif + NH * NH;  // [hout][hin] f32 (exact slow path)
    float b1[4], b02[4];
#pragma unroll
    for (int j = 0; j < 4; j++) {
        b1[j] = b_lif[NH + h4 + j];
        b02[j] = 0.2f * b1[j];
    }
    // bias-safe: 0.8*v + b02 < 1 for all v < 1 (with margin) -> layer-1 can
    // never spike on zero input; its update may be deferred in closed form.
    const bool bias_safe =
        __all_sync(0xFFFFFFFFu, (b02[0] < 0.1999f) && (b02[1] < 0.1999f) &&
                                    (b02[2] < 0.1999f) && (b02[3] < 0.1999f));

    float v0[4] = {0.f, 0.f, 0.f, 0.f};
    float v1[4] = {0.f, 0.f, 0.f, 0.f};
    float acc[4] = {0.f, 0.f, 0.f, 0.f};
    int t_last = 0;  // (bias_safe) v1 is materialized through substep t_last-1

    const int* myids = idss + warp * NT;
    const char* Qb = (const char*)Qs + h4 * 4;

    __syncthreads();

    // =================== time loop (no block syncs) ===================
    for (int tb = 0; tb < NT / 4; tb++) {
        const int4 idv = *(const int4*)(myids + tb * 4);
        const int idk[4] = {idv.x, idv.y, idv.z, idv.w};
#pragma unroll
        for (int k = 0; k < 4; k++) {
            const int t = tb * 4 + k;
            const float4 q = *(const float4*)(Qb + (idk[k] << 9));
            float n0 = fmaf(0.8f, v0[0], q.x);
            float n1 = fmaf(0.8f, v0[1], q.y);
            float n2 = fmaf(0.8f, v0[2], q.z);
            float n3 = fmaf(0.8f, v0[3], q.w);
            const float mx = fmaxf(fmaxf(n0, n1), fmaxf(n2, n3));
            const unsigned wspike =
                __any_sync(0xFFFFFFFFu, mx >= 1.0f);

            if (wspike) {
                // ---------- SLOW SUBSTEP (warp-local, exact f32) ----------
                // materialize deferred v1: v = fp + 0.8^n (v - fp), fp = 5*b02
                if (bias_safe) {
                    const float d = pow08[t - t_last];
#pragma unroll
                    for (int j = 0; j < 4; j++) {
                        const float fp = 5.0f * b02[j];
                        v1[j] = fmaf(d, v1[j] - fp, fp);
                    }
                }
                // spike masks: bit l of bm[j] <-> h_in = l*4 + j
                unsigned bm[4];
                bm[0] = __ballot_sync(0xFFFFFFFFu, n0 >= 1.0f);
                bm[1] = __ballot_sync(0xFFFFFFFFu, n1 >= 1.0f);
                bm[2] = __ballot_sync(0xFFFFFFFFu, n2 >= 1.0f);
                bm[3] = __ballot_sync(0xFFFFFFFFu, n3 >= 1.0f);
                n0 = (n0 >= 1.0f) ? 0.f : n0;
                n1 = (n1 >= 1.0f) ? 0.f : n1;
                n2 = (n2 >= 1.0f) ? 0.f : n2;
                n3 = (n3 >= 1.0f) ? 0.f : n3;

                // cur[hout] = sum over spiked hin of W1[hout, hin]
                float cur[4] = {0.f, 0.f, 0.f, 0.f};
#pragma unroll
                for (int w = 0; w < 4; w++) {
                    unsigned mm = bm[w];
                    while (mm) {
                        const int l = __ffs(mm) - 1;
                        mm &= mm - 1;
                        const float* col = W1 + (l * 4 + w);
                        cur[0] += __ldg(col + (h4 + 0) * NH);
                        cur[1] += __ldg(col + (h4 + 1) * NH);
                        cur[2] += __ldg(col + (h4 + 2) * NH);
                        cur[3] += __ldg(col + (h4 + 3) * NH);
                    }
                }
#pragma unroll
                for (int j = 0; j < 4; j++) {
                    const float cc = cur[j] + b1[j];
                    const float vv = 0.8f * v1[j] + 0.2f * cc;
                    const bool s = (vv >= 1.0f);
                    acc[j] += s ? 1.f : 0.f;
                    v1[j] = s ? 0.f : vv;
                }
                t_last = t + 1;
            } else if (!bias_safe) {
                // exact per-substep layer-1 update with zero input
#pragma unroll
                for (int j = 0; j < 4; j++) {
                    const float vv = 0.8f * v1[j] + 0.2f * b1[j];
                    const bool s = (vv >= 1.0f);
                    acc[j] += s ? 1.f : 0.f;
                    v1[j] = s ? 0.f : vv;
                }
            }
            // (bias_safe && !wspike): layer-1 fully deferred - no work

            v0[0] = n0;
            v0[1] = n1;
            v0[2] = n2;
            v0[3] = n3;
        }
    }

    // =================== epilogue: classifier (warp-local) ===================
    const float invT = 1.0f / (float)NT;
    const int b = b0 + warp;
#pragma unroll
    for (int c = 0; c < NC; c++) {
        const float* wc = W_cls + c * NH + h4;
        float p = acc[0] * __ldg(wc + 0) + acc[1] * __ldg(wc + 1) +
                  acc[2] * __ldg(wc + 2) + acc[3] * __ldg(wc + 3);
#pragma unroll
        for (int d = 16; d > 0; d >>= 1)
            p += __shfl_xor_sync(0xFFFFFFFFu, p, d);
        if (lane == 0) out[b * NC + c] = p * invT + b_cls[c];
    }
}

// ---------------------------------------------------------------------------
// Host launcher (graph-capturable: kernel launches only)
// Input order: ids, emb, W_in, b_in, W_lif, b_lif, W_rec(unused), W_cls, b_cls
// ---------------------------------------------------------------------------
extern "C" void kernel_launch(void* const* d_in, const int* in_sizes, int n_in,
                              void* d_out, int out_size) {
    const int* ids = (const int*)d_in[0];
    const float* emb = (const float*)d_in[1];
    const float* W_in = (const float*)d_in[2];
    const float* b_in = (const float*)d_in[3];
    const float* W_lif = (const float*)d_in[4];
    const float* b_lif = (const float*)d_in[5];
    const float* W_cls = (const float*)d_in[7];
    const float* b_cls = (const float*)d_in[8];
    float* out = (float*)d_out;

    cudaFuncSetAttribute(snn_main_kernel,
                         cudaFuncAttributeMaxDynamicSharedMemorySize, SM_BYTES);

    prep_kernel<<<NV, NH>>>(emb, W_in, b_in, W_lif, b_lif);
    snn_main_kernel<<<NB / MB, NTHR, SM_BYTES>>>(ids, W_lif, b_lif, W_cls,
                                                 b_cls, out);
}

// round 7
// speedup vs baseline: 11.5382x; 1.1926x over previous
#include <cuda_runtime.h>
#include <cuda_bf16.h>
#include <cstdint>

// Problem constants
#define NV 128   // vocab
#define NE 64    // embed
#define NH 128   // hidden
#define NC 12    // classes
#define NB 2048  // batch
#define NT 256   // timesteps
#define MB 16    // batch tile per block (one warp per batch)
#define NTHR 512

// Scratch (device global: no allocation allowed)
// g_Q stores 0.2f * ((emb[v]@W_in^T + b_in) @ W_lif0^T + b_lif0)
__device__ float g_Q[NV * NH];

// ---------------------------------------------------------------------------
// Prep kernel: 128 blocks (one per vocab row) x 256 threads.
// 2 threads per output element (k-split), shfl-combined -> short chains.
// ---------------------------------------------------------------------------
__global__ __launch_bounds__(256) void prep_kernel(
    const float* __restrict__ emb, const float* __restrict__ W_in,
    const float* __restrict__ b_in, const float* __restrict__ W_lif,
    const float* __restrict__ b_lif) {
    __shared__ float esh[NE];
    __shared__ float psh[NH];
    const int v = blockIdx.x;
    const int tid = threadIdx.x;
    const int h = tid >> 1;
    const int part = tid & 1;

    if (tid < NE) esh[tid] = emb[v * NE + tid];
    __syncthreads();

    // P[h] = emb[v,:] . W_in[h,:] + b_in[h]   (2 threads, 32 MACs each)
    {
        const float* wr = W_in + h * NE + part * 32;
        const float* er = esh + part * 32;
        float a0 = 0.f, a1 = 0.f, a2 = 0.f, a3 = 0.f;
#pragma unroll
        for (int e = 0; e < 32; e += 4) {
            a0 += er[e + 0] * __ldg(wr + e + 0);
            a1 += er[e + 1] * __ldg(wr + e + 1);
            a2 += er[e + 2] * __ldg(wr + e + 2);
            a3 += er[e + 3] * __ldg(wr + e + 3);
        }
        float p = (a0 + a1) + (a2 + a3);
        p += __shfl_xor_sync(0xFFFFFFFFu, p, 1);
        if (part == 0) psh[h] = p + b_in[h];
    }
    __syncthreads();

    // Q[v,h] = 0.2 * (P . W_lif0[h,:] + b_lif0[h])  (2 threads, 64 MACs each)
    {
        const float* wr = W_lif + h * NH + part * 64;
        const float* pr = psh + part * 64;
        float a0 = 0.f, a1 = 0.f, a2 = 0.f, a3 = 0.f;
#pragma unroll
        for (int i = 0; i < 64; i += 4) {
            a0 += pr[i + 0] * __ldg(wr + i + 0);
            a1 += pr[i + 1] * __ldg(wr + i + 1);
            a2 += pr[i + 2] * __ldg(wr + i + 2);
            a3 += pr[i + 3] * __ldg(wr + i + 3);
        }
        float q = (a0 + a1) + (a2 + a3);
        q += __shfl_xor_sync(0xFFFFFFFFu, q, 1);
        if (part == 0) g_Q[v * NH + h] = 0.2f * (q + b_lif[h]);
    }
}

// smem layout (dynamic):
//   [0     , 65536)  Q table (128*128 f32, pre-scaled by 0.2)
//   [65536 , 81920)  ids     (16*256 i32)
//   [81920 , 82948)  pow08   (257 f32)
#define SM_BYTES 82960

__global__ __launch_bounds__(NTHR, 1) void snn_main_kernel(
    const int* __restrict__ ids, const float* __restrict__ W_lif,
    const float* __restrict__ b_lif, const float* __restrict__ W_cls,
    const float* __restrict__ b_cls, float* __restrict__ out) {
    extern __shared__ char smem[];
    float* Qs = (float*)smem;
    int* idss = (int*)(smem + 65536);
    float* pow08 = (float*)(smem + 81920);

    const int tid = threadIdx.x;
    const int lane = tid & 31;
    const int warp = tid >> 5;  // warp == batch within tile (0..15)
    const int b0 = blockIdx.x * MB;
    const int h4 = lane * 4;    // this thread's 4 hidden dims (both layers)

    // ---- cooperative smem fills ----
    {
        const float4* src = (const float4*)g_Q;
        float4* dst = (float4*)Qs;
#pragma unroll
        for (int i = tid; i < NV * NH / 4; i += NTHR) dst[i] = src[i];
    }
    {
        const int4* src = (const int4*)(ids + b0 * NT);
        int4* dst = (int4*)idss;
#pragma unroll
        for (int i = tid; i < MB * NT / 4; i += NTHR) dst[i] = src[i];
    }
    // 0.8^n table via repeated squaring (used only on rare spike events)
    if (tid <= NT) {
        float p = 1.f, b = 0.8f;
        int n = tid;
#pragma unroll
        for (int k = 0; k < 9; k++) {
            if (n & 1) p *= b;
            b *= b;
            n >>= 1;
        }
        pow08[tid] = p;
    }

    // layer-1 per-thread constants
    const float* W1 = W_lif + NH * NH;  // [hout][hin] f32 (exact slow path)
    float b1[4], b02[4];
#pragma unroll
    for (int j = 0; j < 4; j++) {
        b1[j] = b_lif[NH + h4 + j];
        b02[j] = 0.2f * b1[j];
    }
    // bias-safe: 0.8*v + b02 < 1 for all v < 1 (with margin) -> layer-1 can
    // never spike on zero input; its update may be deferred in closed form.
    const bool bias_safe =
        __all_sync(0xFFFFFFFFu, (b02[0] < 0.1999f) && (b02[1] < 0.1999f) &&
                                    (b02[2] < 0.1999f) && (b02[3] < 0.1999f));

    float v0[4] = {0.f, 0.f, 0.f, 0.f};
    float v1[4] = {0.f, 0.f, 0.f, 0.f};
    float acc[4] = {0.f, 0.f, 0.f, 0.f};
    int t_last = 0;  // (bias_safe) v1 materialized through substep t_last-1

    const int* myids = idss + warp * NT;
    const char* Qb = (const char*)Qs + h4 * 4;

    __syncthreads();

    // =================== time loop: 64 groups of 4 substeps ===============
    for (int tb = 0; tb < NT / 4; tb++) {
        const int4 idv = *(const int4*)(myids + tb * 4);
        // hoisted Q loads (addresses independent of membrane state)
        float4 qs[4];
        qs[0] = *(const float4*)(Qb + (idv.x << 9));
        qs[1] = *(const float4*)(Qb + (idv.y << 9));
        qs[2] = *(const float4*)(Qb + (idv.z << 9));
        qs[3] = *(const float4*)(Qb + (idv.w << 9));

        // save state, run 4 reset-free substeps tracking the running max.
        // (exact detector: no-reset trajectory == true trajectory up to the
        //  first spike, so "any >= 1" over the group is a precise test)
        const float s0 = v0[0], s1 = v0[1], s2 = v0[2], s3 = v0[3];
        float mx = -1e30f;
#pragma unroll
        for (int k = 0; k < 4; k++) {
            v0[0] = fmaf(0.8f, v0[0], qs[k].x);
            v0[1] = fmaf(0.8f, v0[1], qs[k].y);
            v0[2] = fmaf(0.8f, v0[2], qs[k].z);
            v0[3] = fmaf(0.8f, v0[3], qs[k].w);
            mx = fmaxf(mx, fmaxf(fmaxf(v0[0], v0[1]), fmaxf(v0[2], v0[3])));
        }

        if (__any_sync(0xFFFFFFFFu, mx >= 1.0f)) {
            // ---------- SLOW GROUP (warp-local, exact f32) ----------
            v0[0] = s0;
            v0[1] = s1;
            v0[2] = s2;
            v0[3] = s3;
            // materialize deferred v1 to the start of this group
            if (bias_safe) {
                const float d = pow08[tb * 4 - t_last];
#pragma unroll
                for (int j = 0; j < 4; j++) {
                    const float fp = 5.0f * b02[j];
                    v1[j] = fmaf(d, v1[j] - fp, fp);
                }
            }
#pragma unroll
            for (int k = 0; k < 4; k++) {
                float n0 = fmaf(0.8f, v0[0], qs[k].x);
                float n1 = fmaf(0.8f, v0[1], qs[k].y);
                float n2 = fmaf(0.8f, v0[2], qs[k].z);
                float n3 = fmaf(0.8f, v0[3], qs[k].w);
                // spike masks: bit l of bm[j] <-> h_in = l*4 + j
                unsigned bm[4];
                bm[0] = __ballot_sync(0xFFFFFFFFu, n0 >= 1.0f);
                bm[1] = __ballot_sync(0xFFFFFFFFu, n1 >= 1.0f);
                bm[2] = __ballot_sync(0xFFFFFFFFu, n2 >= 1.0f);
                bm[3] = __ballot_sync(0xFFFFFFFFu, n3 >= 1.0f);
                v0[0] = (n0 >= 1.0f) ? 0.f : n0;
                v0[1] = (n1 >= 1.0f) ? 0.f : n1;
                v0[2] = (n2 >= 1.0f) ? 0.f : n2;
                v0[3] = (n3 >= 1.0f) ? 0.f : n3;

                // cur[hout] = sum over spiked hin of W1[hout, hin]
                float cur[4] = {0.f, 0.f, 0.f, 0.f};
#pragma unroll
                for (int w = 0; w < 4; w++) {
                    unsigned mm = bm[w];
                    while (mm) {
                        const int l = __ffs(mm) - 1;
                        mm &= mm - 1;
                        const float* col = W1 + (l * 4 + w);
                        cur[0] += __ldg(col + (h4 + 0) * NH);
                        cur[1] += __ldg(col + (h4 + 1) * NH);
                        cur[2] += __ldg(col + (h4 + 2) * NH);
                        cur[3] += __ldg(col + (h4 + 3) * NH);
                    }
                }
#pragma unroll
                for (int j = 0; j < 4; j++) {
                    const float cc = cur[j] + b1[j];
                    const float vv = 0.8f * v1[j] + 0.2f * cc;
                    const bool s = (vv >= 1.0f);
                    acc[j] += s ? 1.f : 0.f;
                    v1[j] = s ? 0.f : vv;
                }
            }
            t_last = tb * 4 + 4;
        } else if (!bias_safe) {
            // exact per-substep layer-1 update with zero input
#pragma unroll
            for (int k = 0; k < 4; k++)
#pragma unroll
                for (int j = 0; j < 4; j++) {
                    const float vv = 0.8f * v1[j] + 0.2f * b1[j];
                    const bool s = (vv >= 1.0f);
                    acc[j] += s ? 1.f : 0.f;
                    v1[j] = s ? 0.f : vv;
                }
        }
        // (bias_safe && no spikes): layer-1 fully deferred - no work
    }

    // =================== epilogue: classifier (warp-local) ===================
    const float invT = 1.0f / (float)NT;
    const int b = b0 + warp;
#pragma unroll
    for (int c = 0; c < NC; c++) {
        const float* wc = W_cls + c * NH + h4;
        float p = acc[0] * __ldg(wc + 0) + acc[1] * __ldg(wc + 1) +
                  acc[2] * __ldg(wc + 2) + acc[3] * __ldg(wc + 3);
#pragma unroll
        for (int d = 16; d > 0; d >>= 1)
            p += __shfl_xor_sync(0xFFFFFFFFu, p, d);
        if (lane == 0) out[b * NC + c] = p * invT + b_cls[c];
    }
}

// ---------------------------------------------------------------------------
// Host launcher (graph-capturable: kernel launches only)
// Input order: ids, emb, W_in, b_in, W_lif, b_lif, W_rec(unused), W_cls, b_cls
// ---------------------------------------------------------------------------
extern "C" void kernel_launch(void* const* d_in, const int* in_sizes, int n_in,
                              void* d_out, int out_size) {
    const int* ids = (const int*)d_in[0];
    const float* emb = (const float*)d_in[1];
    const float* W_in = (const float*)d_in[2];
    const float* b_in = (const float*)d_in[3];
    const float* W_lif = (const float*)d_in[4];
    const float* b_lif = (const float*)d_in[5];
    const float* W_cls = (const float*)d_in[7];
    const float* b_cls = (const float*)d_in[8];
    float* out = (float*)d_out;

    cudaFuncSetAttribute(snn_main_kernel,
                         cudaFuncAttributeMaxDynamicSharedMemorySize, SM_BYTES);

    prep_kernel<<<NV, 256>>>(emb, W_in, b_in, W_lif, b_lif);
    snn_main_kernel<<<NB / MB, NTHR, SM_BYTES>>>(ids, W_lif, b_lif, W_cls,
                                                 b_cls, out);
}

// round 8
// speedup vs baseline: 14.0554x; 1.2182x over previous
#include <cuda_runtime.h>
#include <cstdint>

// Problem constants
#define NV 128   // vocab
#define NE 64    // embed
#define NH 128   // hidden
#define NC 12    // classes
#define NB 2048  // batch
#define NT 256   // timesteps
#define MB 16    // batch tile per block (one warp per batch)
#define NTHR 512
#define THRESH 0.9995f

// Scratch (device globals: no allocation allowed)
// g_Q stores 0.2f * ((emb[v]@W_in^T + b_in) @ W_lif0^T + b_lif0)
__device__ float g_Q[NV * NH];
__device__ float g_M[NV];  // per-vocab row max of g_Q

// ---------------------------------------------------------------------------
// Prep kernel: 128 blocks (one per vocab row) x 512 threads.
// 4 threads per output element (k-split), shfl-combined. Also emits g_M.
// ---------------------------------------------------------------------------
__global__ __launch_bounds__(NTHR) void prep_kernel(
    const float* __restrict__ emb, const float* __restrict__ W_in,
    const float* __restrict__ b_in, const float* __restrict__ W_lif,
    const float* __restrict__ b_lif) {
    __shared__ float esh[NE];
    __shared__ float psh[NH];
    __shared__ float qsh[NH];
    const int v = blockIdx.x;
    const int tid = threadIdx.x;
    const int h = tid >> 2;
    const int part = tid & 3;

    if (tid < NE) esh[tid] = emb[v * NE + tid];
    __syncthreads();

    // P[h] = emb[v,:] . W_in[h,:] + b_in[h]   (4 threads, 16 MACs each)
    {
        const float* wr = W_in + h * NE + part * 16;
        const float* er = esh + part * 16;
        float a0 = 0.f, a1 = 0.f, a2 = 0.f, a3 = 0.f;
#pragma unroll
        for (int e = 0; e < 16; e += 4) {
            a0 += er[e + 0] * __ldg(wr + e + 0);
            a1 += er[e + 1] * __ldg(wr + e + 1);
            a2 += er[e + 2] * __ldg(wr + e + 2);
            a3 += er[e + 3] * __ldg(wr + e + 3);
        }
        float p = (a0 + a1) + (a2 + a3);
        p += __shfl_xor_sync(0xFFFFFFFFu, p, 1);
        p += __shfl_xor_sync(0xFFFFFFFFu, p, 2);
        if (part == 0) psh[h] = p + b_in[h];
    }
    __syncthreads();

    // Q[v,h] = 0.2 * (P . W_lif0[h,:] + b_lif0[h])  (4 threads, 32 MACs each)
    {
        const float* wr = W_lif + h * NH + part * 32;
        const float* pr = psh + part * 32;
        float a0 = 0.f, a1 = 0.f, a2 = 0.f, a3 = 0.f;
#pragma unroll
        for (int i = 0; i < 32; i += 4) {
            a0 += pr[i + 0] * __ldg(wr + i + 0);
            a1 += pr[i + 1] * __ldg(wr + i + 1);
            a2 += pr[i + 2] * __ldg(wr + i + 2);
            a3 += pr[i + 3] * __ldg(wr + i + 3);
        }
        float q = (a0 + a1) + (a2 + a3);
        q += __shfl_xor_sync(0xFFFFFFFFu, q, 1);
        q += __shfl_xor_sync(0xFFFFFFFFu, q, 2);
        if (part == 0) {
            const float qq = 0.2f * (q + b_lif[h]);
            g_Q[v * NH + h] = qq;
            qsh[h] = qq;
        }
    }
    __syncthreads();

    // M[v] = max_h qsh[h]  (one warp)
    if (tid < 32) {
        float m = fmaxf(fmaxf(qsh[tid], qsh[tid + 32]),
                        fmaxf(qsh[tid + 64], qsh[tid + 96]));
#pragma unroll
        for (int d = 16; d > 0; d >>= 1)
            m = fmaxf(m, __shfl_xor_sync(0xFFFFFFFFu, m, d));
        if (tid == 0) g_M[v] = m;
    }
}

// ---------------------------------------------------------------------------
// Main kernel: one warp per batch. Fast path = warp-uniform scalar bound.
// ---------------------------------------------------------------------------
__global__ __launch_bounds__(NTHR, 1) void snn_main_kernel(
    const int* __restrict__ ids, const float* __restrict__ W_lif,
    const float* __restrict__ b_lif, const float* __restrict__ W_cls,
    const float* __restrict__ b_cls, float* __restrict__ out) {
    __shared__ int idss[MB * NT];   // 16 KB
    __shared__ float Ms[NV];        // 512 B

    const int tid = threadIdx.x;
    const int lane = tid & 31;
    const int warp = tid >> 5;  // warp == batch within tile (0..15)
    const int b0 = blockIdx.x * MB;
    const int h4 = lane * 4;    // this thread's 4 hidden dims (both layers)

    // ---- cooperative smem fills ----
    {
        const int4* src = (const int4*)(ids + b0 * NT);
        int4* dst = (int4*)idss;
#pragma unroll
        for (int i = tid; i < MB * NT / 4; i += NTHR) dst[i] = src[i];
    }
    if (tid < NV / 4) ((float4*)Ms)[tid] = ((const float4*)g_M)[tid];

    // layer-1 per-thread constants
    const float* W1 = W_lif + NH * NH;  // [hout][hin] f32 (exact slow path)
    float b1[4];
#pragma unroll
    for (int j = 0; j < 4; j++) b1[j] = b_lif[NH + h4 + j];
    // bias-safe: layer-1 cannot spike on zero input (0.8v + 0.2b < 1, v < 1)
    const bool bias_safe = __all_sync(
        0xFFFFFFFFu, (0.2f * b1[0] < 0.19999f) && (0.2f * b1[1] < 0.19999f) &&
                         (0.2f * b1[2] < 0.19999f) && (0.2f * b1[3] < 0.19999f));

    // exact state, valid at substep tck (frozen during fast path)
    float v0[4] = {0.f, 0.f, 0.f, 0.f};
    float v1[4] = {0.f, 0.f, 0.f, 0.f};
    float acc[4] = {0.f, 0.f, 0.f, 0.f};
    int tck = 0;

    // warp-uniform upper bound on all 128 layer-0 membranes of this batch
    float u = 0.f;

    const int* myids = idss + warp * NT;

    __syncthreads();

    // =================== time loop: 64 groups of 4 substeps ===============
    for (int tb = 0; tb < NT / 4; tb++) {
        const int4 idv = *(const int4*)(myids + tb * 4);
        const float m0 = Ms[idv.x];
        const float m1 = Ms[idv.y];
        const float m2 = Ms[idv.z];
        const float m3 = Ms[idv.w];
        const float u0 = fmaf(0.8f, u, m0);
        const float u1 = fmaf(0.8f, u0, m1);
        const float u2 = fmaf(0.8f, u1, m2);
        const float u3 = fmaf(0.8f, u2, m3);
        const float mx = fmaxf(fmaxf(u0, u1), fmaxf(u2, u3));
        u = u3;

        if (!bias_safe || mx >= THRESH) {
            // ---------- EXACT REPLAY [tck, end of this group) ----------
            const int tend = tb * 4 + 4;
            for (int t = tck; t < tend; t++) {
                const int id = myids[t];
                const float4 q =
                    __ldg((const float4*)(g_Q + id * NH + h4));
                float n0 = fmaf(0.8f, v0[0], q.x);
                float n1 = fmaf(0.8f, v0[1], q.y);
                float n2 = fmaf(0.8f, v0[2], q.z);
                float n3 = fmaf(0.8f, v0[3], q.w);
                // spike masks: bit l of bm[j] <-> h_in = l*4 + j
                unsigned bm[4];
                bm[0] = __ballot_sync(0xFFFFFFFFu, n0 >= 1.0f);
                bm[1] = __ballot_sync(0xFFFFFFFFu, n1 >= 1.0f);
                bm[2] = __ballot_sync(0xFFFFFFFFu, n2 >= 1.0f);
                bm[3] = __ballot_sync(0xFFFFFFFFu, n3 >= 1.0f);
                v0[0] = (n0 >= 1.0f) ? 0.f : n0;
                v0[1] = (n1 >= 1.0f) ? 0.f : n1;
                v0[2] = (n2 >= 1.0f) ? 0.f : n2;
                v0[3] = (n3 >= 1.0f) ? 0.f : n3;

                // cur[hout] = sum over spiked hin of W1[hout, hin]
                float cur[4] = {0.f, 0.f, 0.f, 0.f};
#pragma unroll
                for (int w = 0; w < 4; w++) {
                    unsigned mm = bm[w];
                    while (mm) {
                        const int l = __ffs(mm) - 1;
                        mm &= mm - 1;
                        const float* col = W1 + (l * 4 + w);
                        cur[0] += __ldg(col + (h4 + 0) * NH);
                        cur[1] += __ldg(col + (h4 + 1) * NH);
                        cur[2] += __ldg(col + (h4 + 2) * NH);
                        cur[3] += __ldg(col + (h4 + 3) * NH);
                    }
                }
#pragma unroll
                for (int j = 0; j < 4; j++) {
                    const float cc = cur[j] + b1[j];
                    const float vv = 0.8f * v1[j] + 0.2f * cc;
                    const bool s = (vv >= 1.0f);
                    acc[j] += s ? 1.f : 0.f;
                    v1[j] = s ? 0.f : vv;
                }
            }
            tck = tend;
            // rebuild the uniform bound from the exact state
            float w = fmaxf(fmaxf(v0[0], v0[1]), fmaxf(v0[2], v0[3]));
#pragma unroll
            for (int d = 16; d > 0; d >>= 1)
                w = fmaxf(w, __shfl_xor_sync(0xFFFFFFFFu, w, d));
            u = w;
        }
        // fast path: nothing to do — v0/v1 frozen at tck, acc unchanged
    }

    // =================== epilogue: classifier (warp-local) ===================
    const float invT = 1.0f / (float)NT;
    const int b = b0 + warp;
#pragma unroll
    for (int c = 0; c < NC; c++) {
        const float* wc = W_cls + c * NH + h4;
        float p = acc[0] * __ldg(wc + 0) + acc[1] * __ldg(wc + 1) +
                  acc[2] * __ldg(wc + 2) + acc[3] * __ldg(wc + 3);
#pragma unroll
        for (int d = 16; d > 0; d >>= 1)
            p += __shfl_xor_sync(0xFFFFFFFFu, p, d);
        if (lane == 0) out[b * NC + c] = p * invT + b_cls[c];
    }
}

// ---------------------------------------------------------------------------
// Host launcher (graph-capturable: kernel launches only)
// Input order: ids, emb, W_in, b_in, W_lif, b_lif, W_rec(unused), W_cls, b_cls
// ---------------------------------------------------------------------------
extern "C" void kernel_launch(void* const* d_in, const int* in_sizes, int n_in,
                              void* d_out, int out_size) {
    const int* ids = (const int*)d_in[0];
    const float* emb = (const float*)d_in[1];
    const float* W_in = (const float*)d_in[2];
    const float* b_in = (const float*)d_in[3];
    const float* W_lif = (const float*)d_in[4];
    const float* b_lif = (const float*)d_in[5];
    const float* W_cls = (const float*)d_in[7];
    const float* b_cls = (const float*)d_in[8];
    float* out = (float*)d_out;

    prep_kernel<<<NV, NTHR>>>(emb, W_in, b_in, W_lif, b_lif);
    snn_main_kernel<<<NB / MB, NTHR>>>(ids, W_lif, b_lif, W_cls, b_cls, out);
}

// round 9
// speedup vs baseline: 16.5772x; 1.1794x over previous
#include <cuda_runtime.h>
#include <cstdint>

// Problem constants
#define NV 128   // vocab
#define NE 64    // embed
#define NH 128   // hidden
#define NC 12    // classes
#define NB 2048  // batch
#define NT 256   // timesteps
#define MB 16    // batch tile per block (one warp per batch)
#define NTHR 512
#define THRESH 0.9995f
#define FULL 0xFFFFFFFFu

// 0.8^n constants
#define P8_1 0.8f
#define P8_2 0.64f
#define P8_4 0.4096f
#define P8_8 0.16777216f
#define P8_16 0.028147497671065608f
#define P8_32 0.0007922816251426434f

// Scratch (device globals: no allocation allowed)
__device__ float g_Q[NV * NH];  // 0.2*((emb[v]@W_in^T+b_in)@W_lif0^T+b_lif0)
__device__ float g_M[NV];       // row max of g_Q
__device__ unsigned g_cnt;      // epoch-based grid barrier counter (zero-init)

__global__ __launch_bounds__(NTHR, 1) void snn_fused_kernel(
    const int* __restrict__ ids, const float* __restrict__ emb,
    const float* __restrict__ W_in, const float* __restrict__ b_in,
    const float* __restrict__ W_lif, const float* __restrict__ b_lif,
    const float* __restrict__ W_cls, const float* __restrict__ b_cls,
    float* __restrict__ out) {
    __shared__ float esh[NE];
    __shared__ float psh[NH];
    __shared__ float qsh[NH];
    __shared__ float Ms[NV];
    __shared__ int idsh[MB * NT];  // replay-only ids staging (16 KB)

    const int tid = threadIdx.x;
    const int lane = tid & 31;
    const int warp = tid >> 5;  // warp == batch within tile (0..15)
    const int v = blockIdx.x;   // vocab row this block prepares (NV == grid)
    const int b0 = blockIdx.x * MB;
    const int h4 = lane * 4;

    // ============ inline prep: Q[v,:], M[v] (4-way k-split) ============
    if (tid < NE) esh[tid] = emb[v * NE + tid];
    __syncthreads();
    const int hh = tid >> 2;
    const int part = tid & 3;
    {
        const float* wr = W_in + hh * NE + part * 16;
        const float* er = esh + part * 16;
        float a0 = 0.f, a1 = 0.f, a2 = 0.f, a3 = 0.f;
#pragma unroll
        for (int e = 0; e < 16; e += 4) {
            a0 += er[e + 0] * __ldg(wr + e + 0);
            a1 += er[e + 1] * __ldg(wr + e + 1);
            a2 += er[e + 2] * __ldg(wr + e + 2);
            a3 += er[e + 3] * __ldg(wr + e + 3);
        }
        float p = (a0 + a1) + (a2 + a3);
        p += __shfl_xor_sync(FULL, p, 1);
        p += __shfl_xor_sync(FULL, p, 2);
        if (part == 0) psh[hh] = p + b_in[hh];
    }
    __syncthreads();
    {
        const float* wr = W_lif + hh * NH + part * 32;
        const float* pr = psh + part * 32;
        float a0 = 0.f, a1 = 0.f, a2 = 0.f, a3 = 0.f;
#pragma unroll
        for (int i = 0; i < 32; i += 4) {
            a0 += pr[i + 0] * __ldg(wr + i + 0);
            a1 += pr[i + 1] * __ldg(wr + i + 1);
            a2 += pr[i + 2] * __ldg(wr + i + 2);
            a3 += pr[i + 3] * __ldg(wr + i + 3);
        }
        float q = (a0 + a1) + (a2 + a3);
        q += __shfl_xor_sync(FULL, q, 1);
        q += __shfl_xor_sync(FULL, q, 2);
        if (part == 0) {
            const float qq = 0.2f * (q + b_lif[hh]);
            g_Q[v * NH + hh] = qq;
            qsh[hh] = qq;
        }
    }
    __syncthreads();
    if (tid < 32) {
        float m = fmaxf(fmaxf(qsh[tid], qsh[tid + 32]),
                        fmaxf(qsh[tid + 64], qsh[tid + 96]));
#pragma unroll
        for (int d = 16; d > 0; d >>= 1)
            m = fmaxf(m, __shfl_xor_sync(FULL, m, d));
        if (tid == 0) g_M[v] = m;
    }

    // ---- grid barrier: epoch-based counter (self-resets across replays) ----
    if (tid == 0) {
        __threadfence();
        const unsigned old = atomicAdd(&g_cnt, 1u);
        const unsigned target = ((old >> 7) + 1u) << 7;  // 128 blocks/epoch
        volatile unsigned* pc = &g_cnt;
        while (*pc < target) {
        }
        __threadfence();
    }
    __syncthreads();
    if (tid < NV / 4) ((float4*)Ms)[tid] = ((const float4*)g_M)[tid];

    // ---- per-thread layer-1 constants ----
    const float* W1 = W_lif + NH * NH;
    float b1[4];
#pragma unroll
    for (int j = 0; j < 4; j++) b1[j] = b_lif[NH + h4 + j];
    const bool bias_safe = __all_sync(
        FULL, (0.2f * b1[0] < 0.19999f) && (0.2f * b1[1] < 0.19999f) &&
                  (0.2f * b1[2] < 0.19999f) && (0.2f * b1[3] < 0.19999f));

    const int b = b0 + warp;
    // prefetch all 256 ids: lane = timestep within chunk (coalesced)
    int myid[8];
#pragma unroll
    for (int c = 0; c < 8; c++)
        myid[c] = __ldg(ids + b * NT + c * 32 + lane);

    __syncthreads();  // Ms visible

    // ============ phase 1: carry-independent chunk scans ============
    // s_t = sum_{j<=t} 0.8^(t-j) M[id_j] within each 32-step chunk
    float mxs[8], s31[8];
#pragma unroll
    for (int c = 0; c < 8; c++) {
        float s = Ms[myid[c]];
        float o;
        o = __shfl_up_sync(FULL, s, 1);
        if (lane >= 1) s = fmaf(P8_1, o, s);
        o = __shfl_up_sync(FULL, s, 2);
        if (lane >= 2) s = fmaf(P8_2, o, s);
        o = __shfl_up_sync(FULL, s, 4);
        if (lane >= 4) s = fmaf(P8_4, o, s);
        o = __shfl_up_sync(FULL, s, 8);
        if (lane >= 8) s = fmaf(P8_8, o, s);
        o = __shfl_up_sync(FULL, s, 16);
        if (lane >= 16) s = fmaf(P8_16, o, s);
        float m = s;
#pragma unroll
        for (int d = 16; d > 0; d >>= 1)
            m = fmaxf(m, __shfl_xor_sync(FULL, m, d));
        mxs[c] = m;                           // warp-uniform chunk max of s
        s31[c] = __shfl_sync(FULL, s, 31);    // chunk-final scan value
    }

    // ============ phase 2: serial carry + (rare) exact replay ============
    float v0[4] = {0.f, 0.f, 0.f, 0.f};
    float v1[4] = {0.f, 0.f, 0.f, 0.f};
    float acc[4] = {0.f, 0.f, 0.f, 0.f};
    int tck = 0;        // exact state valid through substep tck-1
    float u = 0.f;      // warp-uniform upper bound on all layer-0 membranes
    bool staged = false;

    for (int c = 0; c < 8; c++) {
        // bound >= max_t(s_t + 0.8^(t+1) u) for t in this chunk
        const float bnd = fmaf(0.8f, fmaxf(u, 0.f), mxs[c]);
        if (!bias_safe || bnd >= THRESH) {
            // ---------- EXACT REPLAY [tck, 32*(c+1)) ----------
            if (!staged) {  // stage this warp's ids to smem once
#pragma unroll
                for (int cc = 0; cc < 8; cc++)
                    idsh[warp * NT + cc * 32 + lane] = myid[cc];
                __syncwarp();
                staged = true;
            }
            const int tend = (c + 1) * 32;
            for (int t = tck; t < tend; t++) {
                const int id = idsh[warp * NT + t];
                const float4 q = __ldg((const float4*)(g_Q + id * NH + h4));
                float n0 = fmaf(0.8f, v0[0], q.x);
                float n1 = fmaf(0.8f, v0[1], q.y);
                float n2 = fmaf(0.8f, v0[2], q.z);
                float n3 = fmaf(0.8f, v0[3], q.w);
                unsigned bm[4];
                bm[0] = __ballot_sync(FULL, n0 >= 1.0f);
                bm[1] = __ballot_sync(FULL, n1 >= 1.0f);
                bm[2] = __ballot_sync(FULL, n2 >= 1.0f);
                bm[3] = __ballot_sync(FULL, n3 >= 1.0f);
                v0[0] = (n0 >= 1.0f) ? 0.f : n0;
                v0[1] = (n1 >= 1.0f) ? 0.f : n1;
                v0[2] = (n2 >= 1.0f) ? 0.f : n2;
                v0[3] = (n3 >= 1.0f) ? 0.f : n3;

                float cur[4] = {0.f, 0.f, 0.f, 0.f};
#pragma unroll
                for (int w = 0; w < 4; w++) {
                    unsigned mm = bm[w];
                    while (mm) {
                        const int l = __ffs(mm) - 1;
                        mm &= mm - 1;
                        const float* col = W1 + (l * 4 + w);
                        cur[0] += __ldg(col + (h4 + 0) * NH);
                        cur[1] += __ldg(col + (h4 + 1) * NH);
                        cur[2] += __ldg(col + (h4 + 2) * NH);
                        cur[3] += __ldg(col + (h4 + 3) * NH);
                    }
                }
#pragma unroll
                for (int j = 0; j < 4; j++) {
                    const float cc2 = cur[j] + b1[j];
                    const float vv = 0.8f * v1[j] + 0.2f * cc2;
                    const bool s = (vv >= 1.0f);
                    acc[j] += s ? 1.f : 0.f;
                    v1[j] = s ? 0.f : vv;
                }
            }
            tck = tend;
            // rebuild exact uniform bound
            float w = fmaxf(fmaxf(v0[0], v0[1]), fmaxf(v0[2], v0[3]));
#pragma unroll
            for (int d = 16; d > 0; d >>= 1)
                w = fmaxf(w, __shfl_xor_sync(FULL, w, d));
            u = w;
        } else {
            u = fmaf(P8_32, u, s31[c]);  // exact-scan carry update
        }
    }

    // ============ epilogue ============
    if (tck == 0) {
        // never replayed -> no layer-0 spikes -> acc == 0 -> logits = b_cls
        if (lane < NC) out[b * NC + lane] = b_cls[lane];
    } else {
        const float invT = 1.0f / (float)NT;
#pragma unroll
        for (int cc = 0; cc < NC; cc++) {
            const float* wc = W_cls + cc * NH + h4;
            float p = acc[0] * __ldg(wc + 0) + acc[1] * __ldg(wc + 1) +
                      acc[2] * __ldg(wc + 2) + acc[3] * __ldg(wc + 3);
#pragma unroll
            for (int d = 16; d > 0; d >>= 1)
                p += __shfl_xor_sync(FULL, p, d);
            if (lane == 0) out[b * NC + cc] = p * invT + b_cls[cc];
        }
    }
}

// ---------------------------------------------------------------------------
// Host launcher (graph-capturable: ONE kernel launch)
// Input order: ids, emb, W_in, b_in, W_lif, b_lif, W_rec(unused), W_cls, b_cls
// ---------------------------------------------------------------------------
extern "C" void kernel_launch(void* const* d_in, const int* in_sizes, int n_in,
                              void* d_out, int out_size) {
    const int* ids = (const int*)d_in[0];
    const float* emb = (const float*)d_in[1];
    const float* W_in = (const float*)d_in[2];
    const float* b_in = (const float*)d_in[3];
    const float* W_lif = (const float*)d_in[4];
    const float* b_lif = (const float*)d_in[5];
    const float* W_cls = (const float*)d_in[7];
    const float* b_cls = (const float*)d_in[8];
    float* out = (float*)d_out;

    snn_fused_kernel<<<NB / MB, NTHR>>>(ids, emb, W_in, b_in, W_lif, b_lif,
                                        W_cls, b_cls, out);
}

// round 10
// speedup vs baseline: 29.2132x; 1.7623x over previous
#include <cuda_runtime.h>
#include <cstdint>

// Problem constants
#define NV 128   // vocab
#define NE 64    // embed
#define NH 128   // hidden
#define NC 12    // classes
#define NB 2048  // batch
#define NT 256   // timesteps
#define MB 16    // batch tile per block (one warp per batch)
#define NTHR 512
#define THRESH 0.9995f
#define FULL 0xFFFFFFFFu

// 0.8^n constants
#define P8_1 0.8f
#define P8_2 0.64f
#define P8_4 0.4096f
#define P8_8 0.16777216f
#define P8_16 0.028147497671065608f
#define P8_32 0.0007922816251426434f

// Scratch (device globals: no allocation allowed)
__device__ float g_Q[NV * NH];  // 0.2*((emb[v]@W_in^T+b_in)@W_lif0^T+b_lif0)
__device__ float g_M[NV];       // row max of g_Q
__device__ unsigned g_cnt;      // epoch-based grid barrier counter (zero-init)

__global__ __launch_bounds__(NTHR, 1) void snn_fused_kernel(
    const int* __restrict__ ids, const float* __restrict__ emb,
    const float* __restrict__ W_in, const float* __restrict__ b_in,
    const float* __restrict__ W_lif, const float* __restrict__ b_lif,
    const float* __restrict__ W_cls, const float* __restrict__ b_cls,
    float* __restrict__ out) {
    __shared__ __align__(16) float esh[NE];
    __shared__ __align__(16) float psh[NH];
    __shared__ __align__(16) float qsh[NH];
    __shared__ __align__(16) float Ms[NV];
    __shared__ int idsh[MB * NT];  // replay-only ids staging (16 KB)

    const int tid = threadIdx.x;
    const int lane = tid & 31;
    const int warp = tid >> 5;  // warp == batch within tile (0..15)
    const int v = blockIdx.x;   // vocab row this block prepares (NV == grid)
    const int b0 = blockIdx.x * MB;
    const int h4 = lane * 4;

    // ============ inline prep: Q[v,:], M[v] — COALESCED (lane = k) ========
    if (tid < NE) esh[tid] = emb[v * NE + tid];
    __syncthreads();

    // P[h] = emb[v,:] . W_in[h,:] + b_in[h]
    // warp owns h = warp*8 + r (r=0..7); lanes sweep k (coalesced 128B).
    {
        const float e0 = esh[lane];
        const float e1 = esh[lane + 32];
        float pr[8];
#pragma unroll
        for (int r = 0; r < 8; r++) {
            const int h = warp * 8 + r;
            const float* wr = W_in + h * NE;
            pr[r] = fmaf(__ldg(wr + lane), e0,
                         __ldg(wr + lane + 32) * e1);
        }
#pragma unroll
        for (int r = 0; r < 8; r++) {
#pragma unroll
            for (int d = 16; d > 0; d >>= 1)
                pr[r] += __shfl_xor_sync(FULL, pr[r], d);
            if (lane == 0) {
                const int h = warp * 8 + r;
                psh[h] = pr[r] + b_in[h];
            }
        }
    }
    __syncthreads();

    // Q[v,h] = 0.2 * (P . W_lif0[h,:] + b_lif0[h])
    // lanes read float4 (512B contiguous per row).
    {
        const float4 pv = *(const float4*)(psh + h4);
        float qr[8];
#pragma unroll
        for (int r = 0; r < 8; r++) {
            const int h = warp * 8 + r;
            const float4 wv =
                __ldg((const float4*)(W_lif + h * NH + h4));
            qr[r] = fmaf(wv.x, pv.x,
                         fmaf(wv.y, pv.y, fmaf(wv.z, pv.z, wv.w * pv.w)));
        }
#pragma unroll
        for (int r = 0; r < 8; r++) {
#pragma unroll
            for (int d = 16; d > 0; d >>= 1)
                qr[r] += __shfl_xor_sync(FULL, qr[r], d);
            if (lane == 0) {
                const int h = warp * 8 + r;
                const float qq = 0.2f * (qr[r] + b_lif[h]);
                g_Q[v * NH + h] = qq;
                qsh[h] = qq;
            }
        }
    }
    __syncthreads();
    if (tid < 32) {
        float m = fmaxf(fmaxf(qsh[tid], qsh[tid + 32]),
                        fmaxf(qsh[tid + 64], qsh[tid + 96]));
#pragma unroll
        for (int d = 16; d > 0; d >>= 1)
            m = fmaxf(m, __shfl_xor_sync(FULL, m, d));
        if (tid == 0) g_M[v] = m;
    }

    // ---- grid barrier: epoch-based counter (self-resets across replays) ----
    if (tid == 0) {
        __threadfence();
        const unsigned old = atomicAdd(&g_cnt, 1u);
        const unsigned target = ((old >> 7) + 1u) << 7;  // 128 blocks/epoch
        volatile unsigned* pc = &g_cnt;
        while (*pc < target) {
        }
        __threadfence();
    }
    __syncthreads();
    if (tid < NV / 4) ((float4*)Ms)[tid] = ((const float4*)g_M)[tid];

    // ---- per-thread layer-1 constants ----
    const float* W1 = W_lif + NH * NH;
    float b1[4];
#pragma unroll
    for (int j = 0; j < 4; j++) b1[j] = b_lif[NH + h4 + j];
    const bool bias_safe = __all_sync(
        FULL, (0.2f * b1[0] < 0.19999f) && (0.2f * b1[1] < 0.19999f) &&
                  (0.2f * b1[2] < 0.19999f) && (0.2f * b1[3] < 0.19999f));

    const int b = b0 + warp;
    // prefetch all 256 ids: lane = timestep within chunk (coalesced)
    int myid[8];
#pragma unroll
    for (int c = 0; c < 8; c++)
        myid[c] = __ldg(ids + b * NT + c * 32 + lane);

    __syncthreads();  // Ms visible

    // ============ phase 1: carry-independent chunk scans ============
    // s_t = sum_{j<=t} 0.8^(t-j) M[id_j] within each 32-step chunk
    float mxs[8], s31[8];
#pragma unroll
    for (int c = 0; c < 8; c++) {
        float s = Ms[myid[c]];
        float o;
        o = __shfl_up_sync(FULL, s, 1);
        if (lane >= 1) s = fmaf(P8_1, o, s);
        o = __shfl_up_sync(FULL, s, 2);
        if (lane >= 2) s = fmaf(P8_2, o, s);
        o = __shfl_up_sync(FULL, s, 4);
        if (lane >= 4) s = fmaf(P8_4, o, s);
        o = __shfl_up_sync(FULL, s, 8);
        if (lane >= 8) s = fmaf(P8_8, o, s);
        o = __shfl_up_sync(FULL, s, 16);
        if (lane >= 16) s = fmaf(P8_16, o, s);
        float m = s;
#pragma unroll
        for (int d = 16; d > 0; d >>= 1)
            m = fmaxf(m, __shfl_xor_sync(FULL, m, d));
        mxs[c] = m;                           // warp-uniform chunk max of s
        s31[c] = __shfl_sync(FULL, s, 31);    // chunk-final scan value
    }

    // ============ phase 2: serial carry + (rare) exact replay ============
    float v0[4] = {0.f, 0.f, 0.f, 0.f};
    float v1[4] = {0.f, 0.f, 0.f, 0.f};
    float acc[4] = {0.f, 0.f, 0.f, 0.f};
    int tck = 0;        // exact state valid through substep tck-1
    float u = 0.f;      // warp-uniform upper bound on all layer-0 membranes
    bool staged = false;

    for (int c = 0; c < 8; c++) {
        // bound >= max_t(s_t + 0.8^(t+1) u) for t in this chunk
        const float bnd = fmaf(0.8f, fmaxf(u, 0.f), mxs[c]);
        if (!bias_safe || bnd >= THRESH) {
            // ---------- EXACT REPLAY [tck, 32*(c+1)) ----------
            if (!staged) {  // stage this warp's ids to smem once
#pragma unroll
                for (int cc = 0; cc < 8; cc++)
                    idsh[warp * NT + cc * 32 + lane] = myid[cc];
                __syncwarp();
                staged = true;
            }
            const int tend = (c + 1) * 32;
            for (int t = tck; t < tend; t++) {
                const int id = idsh[warp * NT + t];
                const float4 q = __ldg((const float4*)(g_Q + id * NH + h4));
                float n0 = fmaf(0.8f, v0[0], q.x);
                float n1 = fmaf(0.8f, v0[1], q.y);
                float n2 = fmaf(0.8f, v0[2], q.z);
                float n3 = fmaf(0.8f, v0[3], q.w);
                unsigned bm[4];
                bm[0] = __ballot_sync(FULL, n0 >= 1.0f);
                bm[1] = __ballot_sync(FULL, n1 >= 1.0f);
                bm[2] = __ballot_sync(FULL, n2 >= 1.0f);
                bm[3] = __ballot_sync(FULL, n3 >= 1.0f);
                v0[0] = (n0 >= 1.0f) ? 0.f : n0;
                v0[1] = (n1 >= 1.0f) ? 0.f : n1;
                v0[2] = (n2 >= 1.0f) ? 0.f : n2;
                v0[3] = (n3 >= 1.0f) ? 0.f : n3;

                float cur[4] = {0.f, 0.f, 0.f, 0.f};
#pragma unroll
                for (int w = 0; w < 4; w++) {
                    unsigned mm = bm[w];
                    while (mm) {
                        const int l = __ffs(mm) - 1;
                        mm &= mm - 1;
                        const float* col = W1 + (l * 4 + w);
                        cur[0] += __ldg(col + (h4 + 0) * NH);
                        cur[1] += __ldg(col + (h4 + 1) * NH);
                        cur[2] += __ldg(col + (h4 + 2) * NH);
                        cur[3] += __ldg(col + (h4 + 3) * NH);
                    }
                }
#pragma unroll
                for (int j = 0; j < 4; j++) {
                    const float cc2 = cur[j] + b1[j];
                    const float vv = 0.8f * v1[j] + 0.2f * cc2;
                    const bool s = (vv >= 1.0f);
                    acc[j] += s ? 1.f : 0.f;
                    v1[j] = s ? 0.f : vv;
                }
            }
            tck = tend;
            // rebuild exact uniform bound
            float w = fmaxf(fmaxf(v0[0], v0[1]), fmaxf(v0[2], v0[3]));
#pragma unroll
            for (int d = 16; d > 0; d >>= 1)
                w = fmaxf(w, __shfl_xor_sync(FULL, w, d));
            u = w;
        } else {
            u = fmaf(P8_32, u, s31[c]);  // exact-scan carry update
        }
    }

    // ============ epilogue ============
    if (tck == 0) {
        // never replayed -> no layer-0 spikes -> acc == 0 -> logits = b_cls
        if (lane < NC) out[b * NC + lane] = b_cls[lane];
    } else {
        const float invT = 1.0f / (float)NT;
#pragma unroll
        for (int cc = 0; cc < NC; cc++) {
            const float* wc = W_cls + cc * NH + h4;
            float p = acc[0] * __ldg(wc + 0) + acc[1] * __ldg(wc + 1) +
                      acc[2] * __ldg(wc + 2) + acc[3] * __ldg(wc + 3);
#pragma unroll
            for (int d = 16; d > 0; d >>= 1)
                p += __shfl_xor_sync(FULL, p, d);
            if (lane == 0) out[b * NC + cc] = p * invT + b_cls[cc];
        }
    }
}

// ---------------------------------------------------------------------------
// Host launcher (graph-capturable: ONE kernel launch)
// Input order: ids, emb, W_in, b_in, W_lif, b_lif, W_rec(unused), W_cls, b_cls
// ---------------------------------------------------------------------------
extern "C" void kernel_launch(void* const* d_in, const int* in_sizes, int n_in,
                              void* d_out, int out_size) {
    const int* ids = (const int*)d_in[0];
    const float* emb = (const float*)d_in[1];
    const float* W_in = (const float*)d_in[2];
    const float* b_in = (const float*)d_in[3];
    const float* W_lif = (const float*)d_in[4];
    const float* b_lif = (const float*)d_in[5];
    const float* W_cls = (const float*)d_in[7];
    const float* b_cls = (const float*)d_in[8];
    float* out = (float*)d_out;

    snn_fused_kernel<<<NB / MB, NTHR>>>(ids, emb, W_in, b_in, W_lif, b_lif,
                                        W_cls, b_cls, out);
}

// round 11
// speedup vs baseline: 35.5791x; 1.2179x over previous
#include <cuda_runtime.h>
#include <cstdint>

// Problem constants
#define NV 128   // vocab
#define NE 64    // embed
#define NH 128   // hidden
#define NC 12    // classes
#define NB 2048  // batch
#define NT 256   // timesteps
#define MB 16    // batch tile per block (one warp per batch)
#define NTHR 512
#define THRESH 0.9995f
#define FULL 0xFFFFFFFFu

// 0.8^n constants
#define P8_1 0.8f
#define P8_2 0.64f
#define P8_4 0.4096f
#define P8_8 0.16777216f
#define P8_16 0.028147497671065608f
#define P8_32 0.0007922816251426434f

// Scratch (device globals: no allocation allowed)
__device__ float g_Q[NV * NH];  // 0.2*((emb[v]@W_in^T+b_in)@W_lif0^T+b_lif0)
__device__ float g_M[NV];       // row max of g_Q
__device__ unsigned g_cnt;      // epoch-based grid barrier counter (zero-init)

__global__ __launch_bounds__(NTHR, 1) void snn_fused_kernel(
    const int* __restrict__ ids, const float* __restrict__ emb,
    const float* __restrict__ W_in, const float* __restrict__ b_in,
    const float* __restrict__ W_lif, const float* __restrict__ b_lif,
    const float* __restrict__ W_cls, const float* __restrict__ b_cls,
    float* __restrict__ out) {
    __shared__ __align__(16) float psh[NH];
    __shared__ float wmax[MB];
    __shared__ __align__(16) float Ms[NV];
    __shared__ int idsh[MB * NT];  // replay-only ids staging

    const int tid = threadIdx.x;
    const int lane = tid & 31;
    const int warp = tid >> 5;  // warp == batch within tile (0..15)
    const int v = blockIdx.x;   // vocab row this block prepares (NV == grid)
    const int b0 = blockIdx.x * MB;
    const int h4 = lane * 4;

    // ============ prefetch EVERYTHING (one MLP window) ============
    const float e0 = __ldg(emb + v * NE + lane);
    const float e1 = __ldg(emb + v * NE + 32 + lane);
    float wi0[8], wi1[8];
    float4 wv[8];
#pragma unroll
    for (int r = 0; r < 8; r++) {
        const int h = warp * 8 + r;
        wi0[r] = __ldg(W_in + h * NE + lane);
        wi1[r] = __ldg(W_in + h * NE + 32 + lane);
        wv[r] = __ldg((const float4*)(W_lif + h * NH + h4));
    }
    const float bin = (lane < 8) ? __ldg(b_in + warp * 8 + lane) : 0.f;
    const float bl0 = (lane < 8) ? __ldg(b_lif + warp * 8 + lane) : 0.f;
    float b1[4];
#pragma unroll
    for (int j = 0; j < 4; j++) b1[j] = __ldg(b_lif + NH + h4 + j);
    const float bc = (lane < NC) ? __ldg(b_cls + lane) : 0.f;

    // ============ prep: P = emb[v]@W_in^T + b_in ============
    {
        float pr[8];
#pragma unroll
        for (int r = 0; r < 8; r++) pr[r] = fmaf(wi0[r], e0, wi1[r] * e1);
#pragma unroll
        for (int r = 0; r < 8; r++) {
#pragma unroll
            for (int d = 16; d > 0; d >>= 1)
                pr[r] += __shfl_xor_sync(FULL, pr[r], d);
            if (lane == r) psh[warp * 8 + r] = pr[r] + bin;
        }
    }
    __syncthreads();

    // ============ prep: Q[v,h] = 0.2*(P . W_lif0[h,:] + b_lif0[h]) ========
    {
        const float4 pv = *(const float4*)(psh + h4);
        float qr[8];
#pragma unroll
        for (int r = 0; r < 8; r++)
            qr[r] = fmaf(wv[r].x, pv.x,
                         fmaf(wv[r].y, pv.y,
                              fmaf(wv[r].z, pv.z, wv[r].w * pv.w)));
        float qmine = -1e30f;
#pragma unroll
        for (int r = 0; r < 8; r++) {
#pragma unroll
            for (int d = 16; d > 0; d >>= 1)
                qr[r] += __shfl_xor_sync(FULL, qr[r], d);
            if (lane == r) {
                const float qq = 0.2f * (qr[r] + bl0);
                g_Q[v * NH + warp * 8 + r] = qq;
                qmine = qq;
            }
        }
        // warp row-max (lanes >= 8 hold -inf)
#pragma unroll
        for (int d = 16; d > 0; d >>= 1)
            qmine = fmaxf(qmine, __shfl_xor_sync(FULL, qmine, d));
        if (lane == 0) wmax[warp] = qmine;
    }
    __threadfence();  // release g_Q before the barrier arrive
    __syncthreads();
    if (tid == 0) {
        float m = wmax[0];
#pragma unroll
        for (int w = 1; w < MB; w++) m = fmaxf(m, wmax[w]);
        g_M[v] = m;
        // ---- grid barrier arrive (epoch-based, self-resets on replays) ----
        __threadfence();
        const unsigned old = atomicAdd(&g_cnt, 1u);
        const unsigned target = ((old >> 7) + 1u) << 7;  // 128 blocks/epoch
        volatile unsigned* pc = &g_cnt;
        while (*pc < target) {
        }
        __threadfence();
    }
    __syncthreads();

    // ============ tier 0: global no-spike certificate ============
    // u_t <= sum_j 0.8^j max_v M[v] <= 5*max(M*,0) for every batch/step.
    float gm;
    {
        const float m0 = g_M[lane];
        const float m1 = g_M[lane + 32];
        const float m2 = g_M[lane + 64];
        const float m3 = g_M[lane + 96];
        gm = fmaxf(fmaxf(m0, m1), fmaxf(m2, m3));
#pragma unroll
        for (int d = 16; d > 0; d >>= 1)
            gm = fmaxf(gm, __shfl_xor_sync(FULL, gm, d));
    }
    const bool bias_safe = __all_sync(
        FULL, (0.2f * b1[0] < 0.19999f) && (0.2f * b1[1] < 0.19999f) &&
                  (0.2f * b1[2] < 0.19999f) && (0.2f * b1[3] < 0.19999f));
    const int b = b0 + warp;

    if (bias_safe && 5.0f * fmaxf(gm, 0.f) < THRESH) {
        // no layer-0 spike possible anywhere -> acc == 0 -> logits = b_cls
        if (lane < NC) out[b * NC + lane] = bc;
        return;
    }

    // ============ tier 1+: full scan / replay machinery (exact) ============
    if (tid < NV / 4) ((float4*)Ms)[tid] = ((const float4*)g_M)[tid];
    int myid[8];
#pragma unroll
    for (int c = 0; c < 8; c++)
        myid[c] = __ldg(ids + b * NT + c * 32 + lane);
    __syncthreads();

    // phase 1: carry-independent chunk scans
    float mxs[8], s31[8];
#pragma unroll
    for (int c = 0; c < 8; c++) {
        float s = Ms[myid[c]];
        float o;
        o = __shfl_up_sync(FULL, s, 1);
        if (lane >= 1) s = fmaf(P8_1, o, s);
        o = __shfl_up_sync(FULL, s, 2);
        if (lane >= 2) s = fmaf(P8_2, o, s);
        o = __shfl_up_sync(FULL, s, 4);
        if (lane >= 4) s = fmaf(P8_4, o, s);
        o = __shfl_up_sync(FULL, s, 8);
        if (lane >= 8) s = fmaf(P8_8, o, s);
        o = __shfl_up_sync(FULL, s, 16);
        if (lane >= 16) s = fmaf(P8_16, o, s);
        float m = s;
#pragma unroll
        for (int d = 16; d > 0; d >>= 1)
            m = fmaxf(m, __shfl_xor_sync(FULL, m, d));
        mxs[c] = m;
        s31[c] = __shfl_sync(FULL, s, 31);
    }

    // phase 2: serial carry + (rare) exact replay
    const float* W1 = W_lif + NH * NH;
    float v0[4] = {0.f, 0.f, 0.f, 0.f};
    float v1[4] = {0.f, 0.f, 0.f, 0.f};
    float acc[4] = {0.f, 0.f, 0.f, 0.f};
    int tck = 0;
    float u = 0.f;
    bool staged = false;

    for (int c = 0; c < 8; c++) {
        const float bnd = fmaf(0.8f, fmaxf(u, 0.f), mxs[c]);
        if (!bias_safe || bnd >= THRESH) {
            if (!staged) {
#pragma unroll
                for (int cc = 0; cc < 8; cc++)
                    idsh[warp * NT + cc * 32 + lane] = myid[cc];
                __syncwarp();
                staged = true;
            }
            const int tend = (c + 1) * 32;
            for (int t = tck; t < tend; t++) {
                const int id = idsh[warp * NT + t];
                const float4 q = __ldg((const float4*)(g_Q + id * NH + h4));
                float n0 = fmaf(0.8f, v0[0], q.x);
                float n1 = fmaf(0.8f, v0[1], q.y);
                float n2 = fmaf(0.8f, v0[2], q.z);
                float n3 = fmaf(0.8f, v0[3], q.w);
                unsigned bm[4];
                bm[0] = __ballot_sync(FULL, n0 >= 1.0f);
                bm[1] = __ballot_sync(FULL, n1 >= 1.0f);
                bm[2] = __ballot_sync(FULL, n2 >= 1.0f);
                bm[3] = __ballot_sync(FULL, n3 >= 1.0f);
                v0[0] = (n0 >= 1.0f) ? 0.f : n0;
                v0[1] = (n1 >= 1.0f) ? 0.f : n1;
                v0[2] = (n2 >= 1.0f) ? 0.f : n2;
                v0[3] = (n3 >= 1.0f) ? 0.f : n3;

                float cur[4] = {0.f, 0.f, 0.f, 0.f};
#pragma unroll
                for (int w = 0; w < 4; w++) {
                    unsigned mm = bm[w];
                    while (mm) {
                        const int l = __ffs(mm) - 1;
                        mm &= mm - 1;
                        const float* col = W1 + (l * 4 + w);
                        cur[0] += __ldg(col + (h4 + 0) * NH);
                        cur[1] += __ldg(col + (h4 + 1) * NH);
                        cur[2] += __ldg(col + (h4 + 2) * NH);
                        cur[3] += __ldg(col + (h4 + 3) * NH);
                    }
                }
#pragma unroll
                for (int j = 0; j < 4; j++) {
                    const float cc2 = cur[j] + b1[j];
                    const float vv = 0.8f * v1[j] + 0.2f * cc2;
                    const bool s = (vv >= 1.0f);
                    acc[j] += s ? 1.f : 0.f;
                    v1[j] = s ? 0.f : vv;
                }
            }
            tck = tend;
            float w = fmaxf(fmaxf(v0[0], v0[1]), fmaxf(v0[2], v0[3]));
#pragma unroll
            for (int d = 16; d > 0; d >>= 1)
                w = fmaxf(w, __shfl_xor_sync(FULL, w, d));
            u = w;
        } else {
            u = fmaf(P8_32, u, s31[c]);
        }
    }

    // epilogue
    if (tck == 0) {
        if (lane < NC) out[b * NC + lane] = bc;
    } else {
        const float invT = 1.0f / (float)NT;
#pragma unroll
        for (int cc = 0; cc < NC; cc++) {
            const float* wc = W_cls + cc * NH + h4;
            float p = acc[0] * __ldg(wc + 0) + acc[1] * __ldg(wc + 1) +
                      acc[2] * __ldg(wc + 2) + acc[3] * __ldg(wc + 3);
#pragma unroll
            for (int d = 16; d > 0; d >>= 1)
                p += __shfl_xor_sync(FULL, p, d);
            if (lane == 0) out[b * NC + cc] = p * invT + b_cls[cc];
        }
    }
}

// ---------------------------------------------------------------------------
// Host launcher (graph-capturable: ONE kernel launch)
// Input order: ids, emb, W_in, b_in, W_lif, b_lif, W_rec(unused), W_cls, b_cls
// ---------------------------------------------------------------------------
extern "C" void kernel_launch(void* const* d_in, const int* in_sizes, int n_in,
                              void* d_out, int out_size) {
    const int* ids = (const int*)d_in[0];
    const float* emb = (const float*)d_in[1];
    const float* W_in = (const float*)d_in[2];
    const float* b_in = (const float*)d_in[3];
    const float* W_lif = (const float*)d_in[4];
    const float* b_lif = (const float*)d_in[5];
    const float* W_cls = (const float*)d_in[7];
    const float* b_cls = (const float*)d_in[8];
    float* out = (float*)d_out;

    snn_fused_kernel<<<NB / MB, NTHR>>>(ids, emb, W_in, b_in, W_lif, b_lif,
                                        W_cls, b_cls, out);
}